// round 9
// baseline (speedup 1.0000x reference)
#include <cuda_runtime.h>
#include <cuda_bf16.h>

// Problem constants
#define B_SZ   4096
#define HH     128
#define PHI_D  784
#define H1_D   128
#define H2_D   256
#define L1W    57
#define L2W    29
#define EPS    1e-5f
#define NSPLIT 8
#define SPLIT_OFF (B_SZ * H1_D)

// ---------------- scratch ----------------------------------------------------
__device__ float g_phi[B_SZ * PHI_D];
__device__ float g_h1p[NSPLIT * B_SZ * H1_D];
__device__ float g_h1 [B_SZ * H1_D];
__device__ float g_h2 [B_SZ * H2_D];
__device__ float g_h2w[B_SZ * H2_D];
__device__ float g_sum1[2 * H1_D];
__device__ float g_sq1 [2 * H1_D];
__device__ float g_sum2[2 * H2_D];
__device__ float g_sq2 [2 * H2_D];

// ---------------- K1: foveate via pyramid, low-smem --------------------------
// Patch p: size 14*2^p, window top-left 56-7*2^p: p0->49, p1->42, p2->28, p3->0
__global__ __launch_bounds__(512) void foveate_kernel(const float* __restrict__ x,
                                                      const float* __restrict__ loc) {
    __shared__ float L1[56 * L1W];   // 2x2 sums of window
    __shared__ float L2[28 * L2W];   // 4x4 sums
    __shared__ float ctr[14 * 15];   // patch0 pixels (window offset 49)

    int b = blockIdx.x;
    if (b == 0 && threadIdx.x < 256) {          // zero layer-1 stat accumulators
        g_sum1[threadIdx.x] = 0.f;
        g_sq1[threadIdx.x] = 0.f;
    }
    float lx = loc[2 * b + 0];
    float ly = loc[2 * b + 1];
    int cx = (int)(0.5f * ((lx + 1.0f) * 128.0f));
    int cy = (int)(0.5f * ((ly + 1.0f) * 128.0f));
    int wy0 = cy - 56, wx0 = cx - 56;
    const float* xb = x + (size_t)b * HH * HH;

    auto ld = [&](int gy, int gx) -> float {
        return (gy >= 0 && gy < HH && gx >= 0 && gx < HH) ? xb[gy * HH + gx] : 0.f;
    };

    // L1 directly from global: each window pixel read exactly once
    for (int i = threadIdx.x; i < 56 * 56; i += 512) {
        int r = i / 56, c = i - r * 56;
        int gy = wy0 + 2 * r, gx = wx0 + 2 * c;
        L1[r * L1W + c] = (ld(gy, gx) + ld(gy, gx + 1))
                        + (ld(gy + 1, gx) + ld(gy + 1, gx + 1));
    }
    // center 14x14 (patch0) raw pixels
    if (threadIdx.x < 196) {
        int i = threadIdx.x / 14, j = threadIdx.x - i * 14;
        ctr[i * 15 + j] = ld(wy0 + 49 + i, wx0 + 49 + j);
    }
    __syncthreads();

    for (int i = threadIdx.x; i < 28 * 28; i += 512) {
        int r = i / 28, c = i - r * 28;
        const float* a0 = &L1[(2 * r) * L1W + 2 * c];
        const float* a1 = a0 + L1W;
        L2[r * L2W + c] = (a0[0] + a0[1]) + (a1[0] + a1[1]);
    }
    __syncthreads();

    for (int o = threadIdx.x; o < PHI_D; o += 512) {
        int p   = o / 196;
        int rem = o - p * 196;
        int i   = rem / 14;
        int j   = rem - i * 14;
        float v;
        if (p == 0) {
            v = ctr[i * 15 + j];
        } else if (p == 1) {
            v = L1[(21 + i) * L1W + 21 + j] * 0.25f;
        } else if (p == 2) {
            v = L2[(7 + i) * L2W + 7 + j] * 0.0625f;
        } else {
            const float* q0 = &L2[(2 * i) * L2W + 2 * j];
            const float* q1 = q0 + L2W;
            v = ((q0[0] + q0[1]) + (q1[0] + q1[1])) * (1.0f / 64.0f);
        }
        g_phi[(size_t)b * PHI_D + o] = v;
    }
}

// ---------------- K2: GEMM1 split-K, BM=64 BN=128 BK=16, micro 4x8, db -------
__global__ __launch_bounds__(256) void gemm1_kernel(const float* __restrict__ W) {
    __shared__ float As[2][16][68];
    __shared__ float Bs[2][16][132];
    int s = blockIdx.y;
    int t0 = (s == 0) ? 0 : 7 + 6 * (s - 1);    // 49 tiles: [7,6,6,6,6,6,6,6]
    int nt = (s == 0) ? 7 : 6;
    float* out = g_h1p + (size_t)s * SPLIT_OFF;

    int t = threadIdx.x;
    int rowBase = blockIdx.x * 64;
    int tx = t & 15, ty = t >> 4;
    int lc = t & 15, lr = (t >> 4) << 2;
    int bc = (t & 31) << 2, brr = (t >> 5) << 1;
    float acc[4][8] = {};
    float ar[4]; float4 b0r, b1r;

    // prologue
    {
        int k0 = t0 * 16;
        #pragma unroll
        for (int rr = 0; rr < 4; rr++)
            ar[rr] = g_phi[(size_t)(rowBase + lr + rr) * PHI_D + k0 + lc];
        b0r = *(const float4*)&W[(size_t)(k0 + brr) * H1_D + bc];
        b1r = *(const float4*)&W[(size_t)(k0 + brr + 1) * H1_D + bc];
        #pragma unroll
        for (int rr = 0; rr < 4; rr++) As[0][lc][lr + rr] = ar[rr];
        *(float4*)&Bs[0][brr][bc] = b0r;
        *(float4*)&Bs[0][brr + 1][bc] = b1r;
    }
    __syncthreads();
    int cur = 0;
    for (int i = 0; i < nt; i++) {
        if (i + 1 < nt) {
            int k0 = (t0 + i + 1) * 16;
            #pragma unroll
            for (int rr = 0; rr < 4; rr++)
                ar[rr] = g_phi[(size_t)(rowBase + lr + rr) * PHI_D + k0 + lc];
            b0r = *(const float4*)&W[(size_t)(k0 + brr) * H1_D + bc];
            b1r = *(const float4*)&W[(size_t)(k0 + brr + 1) * H1_D + bc];
        }
        #pragma unroll
        for (int kk = 0; kk < 16; kk++) {
            float4 a  = *(const float4*)&As[cur][kk][ty * 4];
            float4 b0 = *(const float4*)&Bs[cur][kk][tx * 8];
            float4 b1 = *(const float4*)&Bs[cur][kk][tx * 8 + 4];
            float av[4] = {a.x, a.y, a.z, a.w};
            float bv[8] = {b0.x, b0.y, b0.z, b0.w, b1.x, b1.y, b1.z, b1.w};
            #pragma unroll
            for (int rr = 0; rr < 4; rr++)
                #pragma unroll
                for (int cc = 0; cc < 8; cc++)
                    acc[rr][cc] += av[rr] * bv[cc];
        }
        if (i + 1 < nt) {
            int nxt = cur ^ 1;
            #pragma unroll
            for (int rr = 0; rr < 4; rr++) As[nxt][lc][lr + rr] = ar[rr];
            *(float4*)&Bs[nxt][brr][bc] = b0r;
            *(float4*)&Bs[nxt][brr + 1][bc] = b1r;
            __syncthreads();
            cur = nxt;
        }
    }
    #pragma unroll
    for (int rr = 0; rr < 4; rr++) {
        int row = rowBase + ty * 4 + rr;
        *(float4*)&out[(size_t)row * H1_D + tx * 8] =
            make_float4(acc[rr][0], acc[rr][1], acc[rr][2], acc[rr][3]);
        *(float4*)&out[(size_t)row * H1_D + tx * 8 + 4] =
            make_float4(acc[rr][4], acc[rr][5], acc[rr][6], acc[rr][7]);
    }
}

// ---------------- K3: reduce partials -> g_h1 + column stats (both paths) ----
__global__ void stats1_kernel(const float* __restrict__ loc,
                              const float* __restrict__ Ww1) {
    int t = threadIdx.x;
    int row0 = blockIdx.x * 16;
    int col = t & 127;
    int rh = t >> 7;

    if (blockIdx.x == 0 && t < 256) {  // zero layer-2 stat accumulators
        g_sum2[t] = 0.f; g_sum2[t + 256] = 0.f;
        g_sq2[t] = 0.f;  g_sq2[t + 256] = 0.f;
    }

    float s = 0.f, q = 0.f;
    #pragma unroll
    for (int r = 0; r < 16; r += 2) {
        int idx = (row0 + r + rh) * H1_D + col;
        float v = 0.f;
        #pragma unroll
        for (int k = 0; k < NSPLIT; k++) v += g_h1p[idx + k * SPLIT_OFF];
        g_h1[idx] = v;
        s += v; q += v * v;
    }
    atomicAdd(&g_sum1[col], s); atomicAdd(&g_sq1[col], q);

    float w0 = Ww1[col], w1 = Ww1[H1_D + col];
    s = 0.f; q = 0.f;
    #pragma unroll
    for (int r = 0; r < 16; r += 2) {
        int b = row0 + r + rh;
        float v = loc[2 * b] * w0 + loc[2 * b + 1] * w1;
        s += v; q += v * v;
    }
    atomicAdd(&g_sum1[H1_D + col], s); atomicAdd(&g_sq1[H1_D + col], q);
}

// ---------------- K4: GEMM2 BM=64 BN=128 micro 4x8 db; BN inline; stats fused
__global__ __launch_bounds__(256) void gemm2_kernel(
        const float* __restrict__ W2,     // (128,256)
        const float* __restrict__ Ww2,    // (128,256)
        const float* __restrict__ loc,
        const float* __restrict__ Ww1,    // (2,128)
        const float* __restrict__ g1, const float* __restrict__ be1,
        const float* __restrict__ gw1, const float* __restrict__ bew1) {
    __shared__ float As[2][16][68];
    __shared__ float Bs[2][16][132];
    int path = blockIdx.z;
    const float* W   = path ? Ww2  : W2;
    float*       out = path ? g_h2w : g_h2;
    const float* gam = path ? gw1 : g1;
    const float* bet = path ? bew1 : be1;
    int soff = path * H1_D;

    int t = threadIdx.x;
    int rowBase = blockIdx.x * 64;
    int colBase = blockIdx.y * 128;
    int tx = t & 15, ty = t >> 4;
    int lc = t & 15, lr = (t >> 4) << 2;
    int bc = (t & 31) << 2, brr = (t >> 5) << 1;
    float acc[4][8] = {};
    float ar[4]; float4 b0r, b1r;

    float lxv[4], lyv[4];
    if (path) {
        #pragma unroll
        for (int rr = 0; rr < 4; rr++) {
            int row = rowBase + lr + rr;
            lxv[rr] = loc[2 * row];
            lyv[rr] = loc[2 * row + 1];
        }
    }

    // A store with BN+relu for K-tile kt into buffer buf
    auto storeA = [&](int kt, int buf) {
        int kc = kt * 16 + lc;
        float mean = g_sum1[soff + kc] * (1.0f / 4096.0f);
        float var  = g_sq1[soff + kc] * (1.0f / 4096.0f) - mean * mean;
        float sc = gam[kc] * rsqrtf(var + EPS);
        float sh = bet[kc] - mean * sc;
        if (path == 0) {
            #pragma unroll
            for (int rr = 0; rr < 4; rr++)
                As[buf][lc][lr + rr] = fmaxf(ar[rr] * sc + sh, 0.f);
        } else {
            float w0 = Ww1[kc], w1 = Ww1[H1_D + kc];
            #pragma unroll
            for (int rr = 0; rr < 4; rr++)
                As[buf][lc][lr + rr] = fmaxf((lxv[rr] * w0 + lyv[rr] * w1) * sc + sh, 0.f);
        }
    };
    auto loadT = [&](int kt) {
        int k0 = kt * 16;
        if (path == 0) {
            #pragma unroll
            for (int rr = 0; rr < 4; rr++)
                ar[rr] = g_h1[(size_t)(rowBase + lr + rr) * H1_D + k0 + lc];
        }
        b0r = *(const float4*)&W[(size_t)(k0 + brr) * H2_D + colBase + bc];
        b1r = *(const float4*)&W[(size_t)(k0 + brr + 1) * H2_D + colBase + bc];
    };

    loadT(0);
    storeA(0, 0);
    *(float4*)&Bs[0][brr][bc] = b0r;
    *(float4*)&Bs[0][brr + 1][bc] = b1r;
    __syncthreads();
    int cur = 0;
    const int NT = H1_D / 16;   // 8
    for (int i = 0; i < NT; i++) {
        if (i + 1 < NT) loadT(i + 1);
        #pragma unroll
        for (int kk = 0; kk < 16; kk++) {
            float4 a  = *(const float4*)&As[cur][kk][ty * 4];
            float4 b0 = *(const float4*)&Bs[cur][kk][tx * 8];
            float4 b1 = *(const float4*)&Bs[cur][kk][tx * 8 + 4];
            float av[4] = {a.x, a.y, a.z, a.w};
            float bv[8] = {b0.x, b0.y, b0.z, b0.w, b1.x, b1.y, b1.z, b1.w};
            #pragma unroll
            for (int rr = 0; rr < 4; rr++)
                #pragma unroll
                for (int cc = 0; cc < 8; cc++)
                    acc[rr][cc] += av[rr] * bv[cc];
        }
        if (i + 1 < NT) {
            int nxt = cur ^ 1;
            storeA(i + 1, nxt);
            *(float4*)&Bs[nxt][brr][bc] = b0r;
            *(float4*)&Bs[nxt][brr + 1][bc] = b1r;
            __syncthreads();
            cur = nxt;
        }
    }
    #pragma unroll
    for (int rr = 0; rr < 4; rr++) {
        int row = rowBase + ty * 4 + rr;
        *(float4*)&out[(size_t)row * H2_D + colBase + tx * 8] =
            make_float4(acc[rr][0], acc[rr][1], acc[rr][2], acc[rr][3]);
        *(float4*)&out[(size_t)row * H2_D + colBase + tx * 8 + 4] =
            make_float4(acc[rr][4], acc[rr][5], acc[rr][6], acc[rr][7]);
    }

    // fused column stats: combine 4 rows in-register, atomic straight to global.
    #pragma unroll
    for (int cc = 0; cc < 8; cc++) {
        float s = acc[0][cc] + acc[1][cc] + acc[2][cc] + acc[3][cc];
        float q = acc[0][cc] * acc[0][cc] + acc[1][cc] * acc[1][cc]
                + acc[2][cc] * acc[2][cc] + acc[3][cc] * acc[3][cc];
        int col = path * H2_D + colBase + tx * 8 + cc;
        atomicAdd(&g_sum2[col], s);
        atomicAdd(&g_sq2[col], q);
    }
}

// ---------------- K6: out = relu(BN(h2) + BN(h2w)), finalize inline ----------
__global__ void final_kernel(const float* __restrict__ g2, const float* __restrict__ be2,
                             const float* __restrict__ gw2, const float* __restrict__ bew2,
                             float* __restrict__ out) {
    int idx = blockIdx.x * blockDim.x + threadIdx.x;
    int c = idx & 255;
    float m0 = g_sum2[c] * (1.0f / 4096.0f);
    float v0 = g_sq2[c] * (1.0f / 4096.0f) - m0 * m0;
    float s0 = g2[c] * rsqrtf(v0 + EPS);
    float h0 = be2[c] - m0 * s0;
    float m1 = g_sum2[256 + c] * (1.0f / 4096.0f);
    float v1 = g_sq2[256 + c] * (1.0f / 4096.0f) - m1 * m1;
    float s1 = gw2[c] * rsqrtf(v1 + EPS);
    float h1 = bew2[c] - m1 * s1;
    float a = g_h2[idx]  * s0 + h0;
    float b = g_h2w[idx] * s1 + h1;
    out[idx] = fmaxf(a + b, 0.f);
}

// ---------------- launch -----------------------------------------------------
extern "C" void kernel_launch(void* const* d_in, const int* in_sizes, int n_in,
                              void* d_out, int out_size) {
    const float* x        = (const float*)d_in[0];
    const float* loc      = (const float*)d_in[1];
    const float* what_W1  = (const float*)d_in[2];
    const float* what_g1  = (const float*)d_in[4];
    const float* what_be1 = (const float*)d_in[5];
    const float* what_W2  = (const float*)d_in[6];
    const float* what_g2  = (const float*)d_in[8];
    const float* what_be2 = (const float*)d_in[9];
    const float* where_W1  = (const float*)d_in[10];
    const float* where_g1  = (const float*)d_in[12];
    const float* where_be1 = (const float*)d_in[13];
    const float* where_W2  = (const float*)d_in[14];
    const float* where_g2  = (const float*)d_in[16];
    const float* where_be2 = (const float*)d_in[17];
    float* out = (float*)d_out;

    foveate_kernel<<<B_SZ, 512>>>(x, loc);
    gemm1_kernel<<<dim3(B_SZ / 64, NSPLIT), 256>>>(what_W1);
    stats1_kernel<<<256, 256>>>(loc, where_W1);
    gemm2_kernel<<<dim3(B_SZ / 64, 2, 2), 256>>>(
        what_W2, where_W2, loc, where_W1,
        what_g1, what_be1, where_g1, where_be1);
    final_kernel<<<(B_SZ * H2_D) / 512, 512>>>(
        what_g2, what_be2, where_g2, where_be2, out);
}

// round 10
// speedup vs baseline: 1.8544x; 1.8544x over previous
#include <cuda_runtime.h>
#include <cuda_bf16.h>

// Problem constants
#define B_SZ   4096
#define HH     128
#define PHI_D  784
#define H1_D   128
#define H2_D   256
#define L1W    57
#define L2W    29
#define EPS    1e-5f
#define NSPLIT 4
#define SPLIT_OFF (B_SZ * H1_D)

// ---------------- scratch ----------------------------------------------------
__device__ float g_phi[B_SZ * PHI_D];
__device__ float g_h1p[NSPLIT * B_SZ * H1_D];
__device__ float g_h1 [B_SZ * H1_D];
__device__ float g_h2 [B_SZ * H2_D];
__device__ float g_h2w[B_SZ * H2_D];
__device__ float g_sum1[2 * H1_D];
__device__ float g_sq1 [2 * H1_D];
__device__ float g_sum2[2 * H2_D];
__device__ float g_sq2 [2 * H2_D];

// ---------------- K1: foveate via pyramid, low-smem --------------------------
// Patch p: size 14*2^p, window top-left 56-7*2^p: p0->49, p1->42, p2->28, p3->0
__global__ __launch_bounds__(512) void foveate_kernel(const float* __restrict__ x,
                                                      const float* __restrict__ loc) {
    __shared__ float L1[56 * L1W];   // 2x2 sums of window
    __shared__ float L2[28 * L2W];   // 4x4 sums
    __shared__ float ctr[14 * 15];   // patch0 pixels (window offset 49)

    int b = blockIdx.x;
    if (b == 0 && threadIdx.x < 256) {          // zero layer-1 stat accumulators
        g_sum1[threadIdx.x] = 0.f;
        g_sq1[threadIdx.x] = 0.f;
    }
    float lx = loc[2 * b + 0];
    float ly = loc[2 * b + 1];
    int cx = (int)(0.5f * ((lx + 1.0f) * 128.0f));
    int cy = (int)(0.5f * ((ly + 1.0f) * 128.0f));
    int wy0 = cy - 56, wx0 = cx - 56;
    const float* xb = x + (size_t)b * HH * HH;

    auto ld = [&](int gy, int gx) -> float {
        return (gy >= 0 && gy < HH && gx >= 0 && gx < HH) ? xb[gy * HH + gx] : 0.f;
    };

    // L1 directly from global: each window pixel read exactly once
    for (int i = threadIdx.x; i < 56 * 56; i += 512) {
        int r = i / 56, c = i - r * 56;
        int gy = wy0 + 2 * r, gx = wx0 + 2 * c;
        L1[r * L1W + c] = (ld(gy, gx) + ld(gy, gx + 1))
                        + (ld(gy + 1, gx) + ld(gy + 1, gx + 1));
    }
    // center 14x14 (patch0) raw pixels
    if (threadIdx.x < 196) {
        int i = threadIdx.x / 14, j = threadIdx.x - i * 14;
        ctr[i * 15 + j] = ld(wy0 + 49 + i, wx0 + 49 + j);
    }
    __syncthreads();

    for (int i = threadIdx.x; i < 28 * 28; i += 512) {
        int r = i / 28, c = i - r * 28;
        const float* a0 = &L1[(2 * r) * L1W + 2 * c];
        const float* a1 = a0 + L1W;
        L2[r * L2W + c] = (a0[0] + a0[1]) + (a1[0] + a1[1]);
    }
    __syncthreads();

    for (int o = threadIdx.x; o < PHI_D; o += 512) {
        int p   = o / 196;
        int rem = o - p * 196;
        int i   = rem / 14;
        int j   = rem - i * 14;
        float v;
        if (p == 0) {
            v = ctr[i * 15 + j];
        } else if (p == 1) {
            v = L1[(21 + i) * L1W + 21 + j] * 0.25f;
        } else if (p == 2) {
            v = L2[(7 + i) * L2W + 7 + j] * 0.0625f;
        } else {
            const float* q0 = &L2[(2 * i) * L2W + 2 * j];
            const float* q1 = q0 + L2W;
            v = ((q0[0] + q0[1]) + (q1[0] + q1[1])) * (1.0f / 64.0f);
        }
        g_phi[(size_t)b * PHI_D + o] = v;
    }
}

// ---------------- K2: GEMM1 split-K (4), BM=64 BN=128 BK=16, micro 4x8, db ---
__global__ __launch_bounds__(256) void gemm1_kernel(const float* __restrict__ W) {
    __shared__ float As[2][16][68];
    __shared__ float Bs[2][16][132];
    int s = blockIdx.y;
    int t0 = (s == 0) ? 0 : 13 + 12 * (s - 1);  // 49 tiles: [13,12,12,12]
    int nt = (s == 0) ? 13 : 12;
    float* out = g_h1p + (size_t)s * SPLIT_OFF;

    int t = threadIdx.x;
    int rowBase = blockIdx.x * 64;
    int tx = t & 15, ty = t >> 4;
    int lc = t & 15, lr = (t >> 4) << 2;
    int bc = (t & 31) << 2, brr = (t >> 5) << 1;
    float acc[4][8] = {};
    float ar[4]; float4 b0r, b1r;

    // prologue
    {
        int k0 = t0 * 16;
        #pragma unroll
        for (int rr = 0; rr < 4; rr++)
            ar[rr] = g_phi[(size_t)(rowBase + lr + rr) * PHI_D + k0 + lc];
        b0r = *(const float4*)&W[(size_t)(k0 + brr) * H1_D + bc];
        b1r = *(const float4*)&W[(size_t)(k0 + brr + 1) * H1_D + bc];
        #pragma unroll
        for (int rr = 0; rr < 4; rr++) As[0][lc][lr + rr] = ar[rr];
        *(float4*)&Bs[0][brr][bc] = b0r;
        *(float4*)&Bs[0][brr + 1][bc] = b1r;
    }
    __syncthreads();
    int cur = 0;
    for (int i = 0; i < nt; i++) {
        if (i + 1 < nt) {
            int k0 = (t0 + i + 1) * 16;
            #pragma unroll
            for (int rr = 0; rr < 4; rr++)
                ar[rr] = g_phi[(size_t)(rowBase + lr + rr) * PHI_D + k0 + lc];
            b0r = *(const float4*)&W[(size_t)(k0 + brr) * H1_D + bc];
            b1r = *(const float4*)&W[(size_t)(k0 + brr + 1) * H1_D + bc];
        }
        #pragma unroll
        for (int kk = 0; kk < 16; kk++) {
            float4 a  = *(const float4*)&As[cur][kk][ty * 4];
            float4 b0 = *(const float4*)&Bs[cur][kk][tx * 8];
            float4 b1 = *(const float4*)&Bs[cur][kk][tx * 8 + 4];
            float av[4] = {a.x, a.y, a.z, a.w};
            float bv[8] = {b0.x, b0.y, b0.z, b0.w, b1.x, b1.y, b1.z, b1.w};
            #pragma unroll
            for (int rr = 0; rr < 4; rr++)
                #pragma unroll
                for (int cc = 0; cc < 8; cc++)
                    acc[rr][cc] += av[rr] * bv[cc];
        }
        if (i + 1 < nt) {
            int nxt = cur ^ 1;
            #pragma unroll
            for (int rr = 0; rr < 4; rr++) As[nxt][lc][lr + rr] = ar[rr];
            *(float4*)&Bs[nxt][brr][bc] = b0r;
            *(float4*)&Bs[nxt][brr + 1][bc] = b1r;
            __syncthreads();
            cur = nxt;
        }
    }
    #pragma unroll
    for (int rr = 0; rr < 4; rr++) {
        int row = rowBase + ty * 4 + rr;
        *(float4*)&out[(size_t)row * H1_D + tx * 8] =
            make_float4(acc[rr][0], acc[rr][1], acc[rr][2], acc[rr][3]);
        *(float4*)&out[(size_t)row * H1_D + tx * 8 + 4] =
            make_float4(acc[rr][4], acc[rr][5], acc[rr][6], acc[rr][7]);
    }
}

// ---------------- K3: reduce partials -> g_h1 + column stats (both paths) ----
__global__ void stats1_kernel(const float* __restrict__ loc,
                              const float* __restrict__ Ww1) {
    int t = threadIdx.x;
    int row0 = blockIdx.x * 16;
    int col = t & 127;
    int rh = t >> 7;

    if (blockIdx.x == 0 && t < 256) {  // zero layer-2 stat accumulators
        g_sum2[t] = 0.f; g_sum2[t + 256] = 0.f;
        g_sq2[t] = 0.f;  g_sq2[t + 256] = 0.f;
    }

    float s = 0.f, q = 0.f;
    #pragma unroll
    for (int r = 0; r < 16; r += 2) {
        int idx = (row0 + r + rh) * H1_D + col;
        float v = 0.f;
        #pragma unroll
        for (int k = 0; k < NSPLIT; k++) v += g_h1p[idx + k * SPLIT_OFF];
        g_h1[idx] = v;
        s += v; q += v * v;
    }
    atomicAdd(&g_sum1[col], s); atomicAdd(&g_sq1[col], q);

    float w0 = Ww1[col], w1 = Ww1[H1_D + col];
    s = 0.f; q = 0.f;
    #pragma unroll
    for (int r = 0; r < 16; r += 2) {
        int b = row0 + r + rh;
        float v = loc[2 * b] * w0 + loc[2 * b + 1] * w1;
        s += v; q += v * v;
    }
    atomicAdd(&g_sum1[H1_D + col], s); atomicAdd(&g_sq1[H1_D + col], q);
}

// ---------------- K4: GEMM2 BM=64 BN=128 micro 4x8 db; BN inline; stats fused
// Epilogue: smem tree reduction + 128 atomics/CTA (R7 design — direct
// per-thread atomics regressed 4x due to same-address L2 serialization).
__global__ __launch_bounds__(256) void gemm2_kernel(
        const float* __restrict__ W2,     // (128,256)
        const float* __restrict__ Ww2,    // (128,256)
        const float* __restrict__ loc,
        const float* __restrict__ Ww1,    // (2,128)
        const float* __restrict__ g1, const float* __restrict__ be1,
        const float* __restrict__ gw1, const float* __restrict__ bew1) {
    __shared__ float As[2][16][68];
    __shared__ float Bs[2][16][132];
    __shared__ float2 red[16][129];
    int path = blockIdx.z;
    const float* W   = path ? Ww2  : W2;
    float*       out = path ? g_h2w : g_h2;
    const float* gam = path ? gw1 : g1;
    const float* bet = path ? bew1 : be1;
    int soff = path * H1_D;

    int t = threadIdx.x;
    int rowBase = blockIdx.x * 64;
    int colBase = blockIdx.y * 128;
    int tx = t & 15, ty = t >> 4;
    int lc = t & 15, lr = (t >> 4) << 2;
    int bc = (t & 31) << 2, brr = (t >> 5) << 1;
    float acc[4][8] = {};
    float ar[4]; float4 b0r, b1r;

    float lxv[4], lyv[4];
    if (path) {
        #pragma unroll
        for (int rr = 0; rr < 4; rr++) {
            int row = rowBase + lr + rr;
            lxv[rr] = loc[2 * row];
            lyv[rr] = loc[2 * row + 1];
        }
    }

    auto storeA = [&](int kt, int buf) {
        int kc = kt * 16 + lc;
        float mean = g_sum1[soff + kc] * (1.0f / 4096.0f);
        float var  = g_sq1[soff + kc] * (1.0f / 4096.0f) - mean * mean;
        float sc = gam[kc] * rsqrtf(var + EPS);
        float sh = bet[kc] - mean * sc;
        if (path == 0) {
            #pragma unroll
            for (int rr = 0; rr < 4; rr++)
                As[buf][lc][lr + rr] = fmaxf(ar[rr] * sc + sh, 0.f);
        } else {
            float w0 = Ww1[kc], w1 = Ww1[H1_D + kc];
            #pragma unroll
            for (int rr = 0; rr < 4; rr++)
                As[buf][lc][lr + rr] = fmaxf((lxv[rr] * w0 + lyv[rr] * w1) * sc + sh, 0.f);
        }
    };
    auto loadT = [&](int kt) {
        int k0 = kt * 16;
        if (path == 0) {
            #pragma unroll
            for (int rr = 0; rr < 4; rr++)
                ar[rr] = g_h1[(size_t)(rowBase + lr + rr) * H1_D + k0 + lc];
        }
        b0r = *(const float4*)&W[(size_t)(k0 + brr) * H2_D + colBase + bc];
        b1r = *(const float4*)&W[(size_t)(k0 + brr + 1) * H2_D + colBase + bc];
    };

    loadT(0);
    storeA(0, 0);
    *(float4*)&Bs[0][brr][bc] = b0r;
    *(float4*)&Bs[0][brr + 1][bc] = b1r;
    __syncthreads();
    int cur = 0;
    const int NT = H1_D / 16;   // 8
    for (int i = 0; i < NT; i++) {
        if (i + 1 < NT) loadT(i + 1);
        #pragma unroll
        for (int kk = 0; kk < 16; kk++) {
            float4 a  = *(const float4*)&As[cur][kk][ty * 4];
            float4 b0 = *(const float4*)&Bs[cur][kk][tx * 8];
            float4 b1 = *(const float4*)&Bs[cur][kk][tx * 8 + 4];
            float av[4] = {a.x, a.y, a.z, a.w};
            float bv[8] = {b0.x, b0.y, b0.z, b0.w, b1.x, b1.y, b1.z, b1.w};
            #pragma unroll
            for (int rr = 0; rr < 4; rr++)
                #pragma unroll
                for (int cc = 0; cc < 8; cc++)
                    acc[rr][cc] += av[rr] * bv[cc];
        }
        if (i + 1 < NT) {
            int nxt = cur ^ 1;
            storeA(i + 1, nxt);
            *(float4*)&Bs[nxt][brr][bc] = b0r;
            *(float4*)&Bs[nxt][brr + 1][bc] = b1r;
            __syncthreads();
            cur = nxt;
        }
    }
    #pragma unroll
    for (int rr = 0; rr < 4; rr++) {
        int row = rowBase + ty * 4 + rr;
        *(float4*)&out[(size_t)row * H2_D + colBase + tx * 8] =
            make_float4(acc[rr][0], acc[rr][1], acc[rr][2], acc[rr][3]);
        *(float4*)&out[(size_t)row * H2_D + colBase + tx * 8 + 4] =
            make_float4(acc[rr][4], acc[rr][5], acc[rr][6], acc[rr][7]);
    }

    // fused column stats over this block's 64 rows (128 cols)
    __syncthreads();
    #pragma unroll
    for (int cc = 0; cc < 8; cc++) {
        float s = acc[0][cc] + acc[1][cc] + acc[2][cc] + acc[3][cc];
        float q = acc[0][cc] * acc[0][cc] + acc[1][cc] * acc[1][cc]
                + acc[2][cc] * acc[2][cc] + acc[3][cc] * acc[3][cc];
        red[ty][tx * 8 + cc] = make_float2(s, q);
    }
    __syncthreads();
    if (t < 128) {
        float s = 0.f, q = 0.f;
        #pragma unroll
        for (int i = 0; i < 16; i++) {
            float2 v = red[i][t];
            s += v.x; q += v.y;
        }
        int col = path * H2_D + colBase + t;
        atomicAdd(&g_sum2[col], s);
        atomicAdd(&g_sq2[col], q);
    }
}

// ---------------- K6: out = relu(BN(h2) + BN(h2w)), finalize inline ----------
__global__ void final_kernel(const float* __restrict__ g2, const float* __restrict__ be2,
                             const float* __restrict__ gw2, const float* __restrict__ bew2,
                             float* __restrict__ out) {
    int idx = blockIdx.x * blockDim.x + threadIdx.x;
    int c = idx & 255;
    float m0 = g_sum2[c] * (1.0f / 4096.0f);
    float v0 = g_sq2[c] * (1.0f / 4096.0f) - m0 * m0;
    float s0 = g2[c] * rsqrtf(v0 + EPS);
    float h0 = be2[c] - m0 * s0;
    float m1 = g_sum2[256 + c] * (1.0f / 4096.0f);
    float v1 = g_sq2[256 + c] * (1.0f / 4096.0f) - m1 * m1;
    float s1 = gw2[c] * rsqrtf(v1 + EPS);
    float h1 = bew2[c] - m1 * s1;
    float a = g_h2[idx]  * s0 + h0;
    float b = g_h2w[idx] * s1 + h1;
    out[idx] = fmaxf(a + b, 0.f);
}

// ---------------- launch -----------------------------------------------------
extern "C" void kernel_launch(void* const* d_in, const int* in_sizes, int n_in,
                              void* d_out, int out_size) {
    const float* x        = (const float*)d_in[0];
    const float* loc      = (const float*)d_in[1];
    const float* what_W1  = (const float*)d_in[2];
    const float* what_g1  = (const float*)d_in[4];
    const float* what_be1 = (const float*)d_in[5];
    const float* what_W2  = (const float*)d_in[6];
    const float* what_g2  = (const float*)d_in[8];
    const float* what_be2 = (const float*)d_in[9];
    const float* where_W1  = (const float*)d_in[10];
    const float* where_g1  = (const float*)d_in[12];
    const float* where_be1 = (const float*)d_in[13];
    const float* where_W2  = (const float*)d_in[14];
    const float* where_g2  = (const float*)d_in[16];
    const float* where_be2 = (const float*)d_in[17];
    float* out = (float*)d_out;

    foveate_kernel<<<B_SZ, 512>>>(x, loc);
    gemm1_kernel<<<dim3(B_SZ / 64, NSPLIT), 256>>>(what_W1);
    stats1_kernel<<<256, 256>>>(loc, where_W1);
    gemm2_kernel<<<dim3(B_SZ / 64, 2, 2), 256>>>(
        what_W2, where_W2, loc, where_W1,
        what_g1, what_be1, where_g1, where_be1);
    final_kernel<<<(B_SZ * H2_D) / 512, 512>>>(
        what_g2, what_be2, where_g2, where_be2, out);
}

// round 12
// speedup vs baseline: 1.8549x; 1.0003x over previous
#include <cuda_runtime.h>
#include <cstdint>

// Problem constants
#define B_SZ   4096
#define HH     128
#define PHI_D  784
#define H1_D   128
#define H2_D   256
#define L1W    57
#define L2W    29
#define EPS    1e-5f

// ---------------- scratch ----------------------------------------------------
__device__ float g_phi[B_SZ * PHI_D];
__device__ float g_h1 [B_SZ * H1_D];
__device__ float g_h2 [B_SZ * H2_D];
__device__ float g_h2w[B_SZ * H2_D];
__device__ float g_sum1[2 * H1_D];
__device__ float g_sq1 [2 * H1_D];
__device__ float g_sum2[2 * H2_D];
__device__ float g_sq2 [2 * H2_D];

// ---------------- tf32 helpers -----------------------------------------------
__device__ __forceinline__ uint32_t tf32_of(float x) {
    uint32_t r;
    asm("cvt.rna.tf32.f32 %0, %1;" : "=r"(r) : "f"(x));
    return r;
}
// split x ~= hi + lo, both representable in tf32 -> ~2^-21 combined precision
__device__ __forceinline__ void tf32_split(float x, uint32_t& hi, uint32_t& lo) {
    hi = tf32_of(x);
    lo = tf32_of(x - __uint_as_float(hi));
}
__device__ __forceinline__ void mma8(float* c, const uint32_t* a, const uint32_t* b) {
    asm volatile(
        "mma.sync.aligned.m16n8k8.row.col.f32.tf32.tf32.f32 "
        "{%0,%1,%2,%3},{%4,%5,%6,%7},{%8,%9},{%0,%1,%2,%3};"
        : "+f"(c[0]), "+f"(c[1]), "+f"(c[2]), "+f"(c[3])
        : "r"(a[0]), "r"(a[1]), "r"(a[2]), "r"(a[3]), "r"(b[0]), "r"(b[1]));
}

// ---------------- K1: foveate via pyramid, low-smem --------------------------
// Patch p: size 14*2^p, window top-left 56-7*2^p: p0->49, p1->42, p2->28, p3->0
__global__ __launch_bounds__(512) void foveate_kernel(const float* __restrict__ x,
                                                      const float* __restrict__ loc) {
    __shared__ float L1[56 * L1W];
    __shared__ float L2[28 * L2W];
    __shared__ float ctr[14 * 15];

    int b = blockIdx.x;
    if (b == 0 && threadIdx.x < 256) {          // zero layer-1 stat accumulators
        g_sum1[threadIdx.x] = 0.f;
        g_sq1[threadIdx.x] = 0.f;
    }
    float lx = loc[2 * b + 0];
    float ly = loc[2 * b + 1];
    int cx = (int)(0.5f * ((lx + 1.0f) * 128.0f));
    int cy = (int)(0.5f * ((ly + 1.0f) * 128.0f));
    int wy0 = cy - 56, wx0 = cx - 56;
    const float* xb = x + (size_t)b * HH * HH;

    auto ld = [&](int gy, int gx) -> float {
        return (gy >= 0 && gy < HH && gx >= 0 && gx < HH) ? xb[gy * HH + gx] : 0.f;
    };

    for (int i = threadIdx.x; i < 56 * 56; i += 512) {
        int r = i / 56, c = i - r * 56;
        int gy = wy0 + 2 * r, gx = wx0 + 2 * c;
        L1[r * L1W + c] = (ld(gy, gx) + ld(gy, gx + 1))
                        + (ld(gy + 1, gx) + ld(gy + 1, gx + 1));
    }
    if (threadIdx.x < 196) {
        int i = threadIdx.x / 14, j = threadIdx.x - i * 14;
        ctr[i * 15 + j] = ld(wy0 + 49 + i, wx0 + 49 + j);
    }
    __syncthreads();

    for (int i = threadIdx.x; i < 28 * 28; i += 512) {
        int r = i / 28, c = i - r * 28;
        const float* a0 = &L1[(2 * r) * L1W + 2 * c];
        const float* a1 = a0 + L1W;
        L2[r * L2W + c] = (a0[0] + a0[1]) + (a1[0] + a1[1]);
    }
    __syncthreads();

    for (int o = threadIdx.x; o < PHI_D; o += 512) {
        int p   = o / 196;
        int rem = o - p * 196;
        int i   = rem / 14;
        int j   = rem - i * 14;
        float v;
        if (p == 0) {
            v = ctr[i * 15 + j];
        } else if (p == 1) {
            v = L1[(21 + i) * L1W + 21 + j] * 0.25f;
        } else if (p == 2) {
            v = L2[(7 + i) * L2W + 7 + j] * 0.0625f;
        } else {
            const float* q0 = &L2[(2 * i) * L2W + 2 * j];
            const float* q1 = q0 + L2W;
            v = ((q0[0] + q0[1]) + (q1[0] + q1[1])) * (1.0f / 64.0f);
        }
        g_phi[(size_t)b * PHI_D + o] = v;
    }
}

// ---------------- K2: GEMM1 h1 = phi @ W1, 3xTF32 mma ------------------------
// 128 threads (4 warps 2x2). BM=64, BN=32, BK=16. Warp tile 32x16 (2m x 2n).
__global__ __launch_bounds__(128) void gemm1_kernel(const float* __restrict__ W) {
    __shared__ float As[2][64 * 20];   // [m][k], stride 20 -> conflict-free frags
    __shared__ float Bs[2][16 * 40];   // [k][n], N=32 <= 40-8 OK, conflict-free

    int t = threadIdx.x;
    int lane = t & 31, warp = t >> 5;
    int wm = warp >> 1, wn = warp & 1;
    int g = lane >> 2, tg = lane & 3;
    int rowBase = blockIdx.x * 64;
    int colBase = blockIdx.y * 32;

    int ar = t >> 1, ako = (t & 1) * 8;     // A staging: row, k-offset (2xfloat4)
    int bkr = t >> 3, bcc = (t & 7) * 4;    // B staging: k-row (0..15), col (0..28)

    float4 pa0, pa1, pb;
    float c[2][2][4] = {};

    auto fetch = [&](int kt) {
        const float* ap = &g_phi[(size_t)(rowBase + ar) * PHI_D + kt * 16 + ako];
        pa0 = *(const float4*)ap;
        pa1 = *(const float4*)(ap + 4);
        pb  = *(const float4*)&W[(size_t)(kt * 16 + bkr) * H1_D + colBase + bcc];
    };
    auto stage = [&](int buf) {
        float* a = &As[buf][ar * 20 + ako];
        *(float4*)a       = pa0;
        *(float4*)(a + 4) = pa1;
        *(float4*)&Bs[buf][bkr * 40 + bcc] = pb;
    };

    fetch(0); stage(0); __syncthreads();
    const int NT = PHI_D / 16;   // 49
    int cur = 0;
    for (int i = 0; i < NT; i++) {
        if (i + 1 < NT) fetch(i + 1);
        #pragma unroll
        for (int ks = 0; ks < 2; ks++) {
            uint32_t ah[2][4], al[2][4], bh[2][2], bl[2][2];
            #pragma unroll
            for (int mt = 0; mt < 2; mt++) {
                int mrow = wm * 32 + mt * 16;
                #pragma unroll
                for (int r = 0; r < 4; r++) {
                    int row = mrow + g + (r & 1) * 8;
                    int col = ks * 8 + tg + (r >> 1) * 4;
                    tf32_split(As[cur][row * 20 + col], ah[mt][r], al[mt][r]);
                }
            }
            #pragma unroll
            for (int nt = 0; nt < 2; nt++) {
                int ncol = wn * 16 + nt * 8 + g;
                #pragma unroll
                for (int r = 0; r < 2; r++)
                    tf32_split(Bs[cur][(ks * 8 + tg + r * 4) * 40 + ncol],
                               bh[nt][r], bl[nt][r]);
            }
            #pragma unroll
            for (int mt = 0; mt < 2; mt++)
                #pragma unroll
                for (int nt = 0; nt < 2; nt++) {
                    mma8(c[mt][nt], ah[mt], bh[nt]);
                    mma8(c[mt][nt], ah[mt], bl[nt]);
                    mma8(c[mt][nt], al[mt], bh[nt]);
                }
        }
        if (i + 1 < NT) {
            int nxt = cur ^ 1;
            stage(nxt);
            __syncthreads();
            cur = nxt;
        }
    }
    #pragma unroll
    for (int mt = 0; mt < 2; mt++) {
        int r0 = rowBase + wm * 32 + mt * 16 + g;
        #pragma unroll
        for (int nt = 0; nt < 2; nt++) {
            int col = colBase + wn * 16 + nt * 8 + 2 * tg;
            *(float2*)&g_h1[(size_t)r0 * H1_D + col] =
                make_float2(c[mt][nt][0], c[mt][nt][1]);
            *(float2*)&g_h1[(size_t)(r0 + 8) * H1_D + col] =
                make_float2(c[mt][nt][2], c[mt][nt][3]);
        }
    }
}

// ---------------- K3: column stats of h1 (+ where path); zero sum2 -----------
__global__ void stats1_kernel(const float* __restrict__ loc,
                              const float* __restrict__ Ww1) {
    int t = threadIdx.x;
    int row0 = blockIdx.x * 16;    // grid 256
    int col = t & 127;
    int rh = t >> 7;

    if (blockIdx.x == 0 && t < 256) {
        g_sum2[t] = 0.f; g_sum2[t + 256] = 0.f;
        g_sq2[t] = 0.f;  g_sq2[t + 256] = 0.f;
    }

    float s = 0.f, q = 0.f;
    #pragma unroll
    for (int r = 0; r < 16; r += 2) {
        float v = g_h1[(row0 + r + rh) * H1_D + col];
        s += v; q += v * v;
    }
    atomicAdd(&g_sum1[col], s); atomicAdd(&g_sq1[col], q);

    float w0 = Ww1[col], w1 = Ww1[H1_D + col];
    s = 0.f; q = 0.f;
    #pragma unroll
    for (int r = 0; r < 16; r += 2) {
        int b = row0 + r + rh;
        float v = loc[2 * b] * w0 + loc[2 * b + 1] * w1;
        s += v; q += v * v;
    }
    atomicAdd(&g_sum1[H1_D + col], s); atomicAdd(&g_sq1[H1_D + col], q);
}

// ---------------- K4: GEMM2 both paths, 3xTF32 mma, BN+relu at staging -------
// 256 threads (8 warps 4x2). BM=128, BN=64, BK=16. Warp tile 32x32 (2m x 4n).
// Bs stride 72 (>= 64 cols + conflict-free); BK=16 keeps smem under 48KB.
__global__ __launch_bounds__(256) void gemm2_kernel(
        const float* __restrict__ W2,     // (128,256)
        const float* __restrict__ Ww2,    // (128,256)
        const float* __restrict__ loc,
        const float* __restrict__ Ww1,    // (2,128)
        const float* __restrict__ g1, const float* __restrict__ be1,
        const float* __restrict__ gw1, const float* __restrict__ bew1) {
    __shared__ float As[2][128 * 20];    // 20.5KB
    __shared__ float Bs[2][16 * 72];     // 9.2KB
    __shared__ float scs[H1_D], shs[H1_D];

    int path = blockIdx.z;
    const float* W   = path ? Ww2  : W2;
    float*       out = path ? g_h2w : g_h2;
    int soff = path * H1_D;

    int t = threadIdx.x;
    int lane = t & 31, warp = t >> 5;
    int wm = warp >> 1, wn = warp & 1;
    int g = lane >> 2, tg = lane & 3;
    int rowBase = blockIdx.x * 128;
    int colBase = blockIdx.y * 64;

    // BN finalize coefficients into smem
    if (t < H1_D) {
        float mean = g_sum1[soff + t] * (1.0f / 4096.0f);
        float var  = g_sq1[soff + t] * (1.0f / 4096.0f) - mean * mean;
        float gam = path ? gw1[t] : g1[t];
        float bet = path ? bew1[t] : be1[t];
        float sc = gam * rsqrtf(var + EPS);
        scs[t] = sc;
        shs[t] = bet - mean * sc;
    }

    int ar = t >> 1, ako = (t & 1) * 8;    // A staging: row (0..127), k-off (2xfloat4)
    int bkr = t >> 4, bcc = (t & 15) * 4;  // B staging: k-row (0..15), col (0..60)
    float lx = 0.f, ly = 0.f;
    if (path) { lx = loc[2 * (rowBase + ar)]; ly = loc[2 * (rowBase + ar) + 1]; }

    float4 pa[2], pb;
    float c[2][4][4] = {};

    auto fetch = [&](int kt) {
        int k0 = kt * 16 + ako;
        if (path == 0) {
            const float* ap = &g_h1[(size_t)(rowBase + ar) * H1_D + k0];
            pa[0] = *(const float4*)ap;
            pa[1] = *(const float4*)(ap + 4);
        } else {
            #pragma unroll
            for (int j = 0; j < 2; j++) {
                float4 w0 = *(const float4*)&Ww1[k0 + j * 4];
                float4 w1 = *(const float4*)&Ww1[H1_D + k0 + j * 4];
                pa[j] = make_float4(lx * w0.x + ly * w1.x, lx * w0.y + ly * w1.y,
                                    lx * w0.z + ly * w1.z, lx * w0.w + ly * w1.w);
            }
        }
        pb = *(const float4*)&W[(size_t)(kt * 16 + bkr) * H2_D + colBase + bcc];
    };
    auto stage = [&](int kt, int buf) {
        int k0 = kt * 16 + ako;
        float* a = &As[buf][ar * 20 + ako];
        #pragma unroll
        for (int j = 0; j < 2; j++) {
            float4 v = pa[j];
            float4 sc4 = *(const float4*)&scs[k0 + j * 4];
            float4 sh4 = *(const float4*)&shs[k0 + j * 4];
            float4 r;
            r.x = fmaxf(v.x * sc4.x + sh4.x, 0.f);
            r.y = fmaxf(v.y * sc4.y + sh4.y, 0.f);
            r.z = fmaxf(v.z * sc4.z + sh4.z, 0.f);
            r.w = fmaxf(v.w * sc4.w + sh4.w, 0.f);
            *(float4*)(a + j * 4) = r;
        }
        *(float4*)&Bs[buf][bkr * 72 + bcc] = pb;
    };

    fetch(0);
    __syncthreads();          // scs/shs visible
    stage(0, 0);
    __syncthreads();
    int cur = 0;
    const int NC = H1_D / 16;   // 8 chunks
    for (int i = 0; i < NC; i++) {
        if (i + 1 < NC) fetch(i + 1);
        #pragma unroll
        for (int ks = 0; ks < 2; ks++) {
            uint32_t ah[2][4], al[2][4], bh[4][2], bl[4][2];
            #pragma unroll
            for (int mt = 0; mt < 2; mt++) {
                int mrow = wm * 32 + mt * 16;
                #pragma unroll
                for (int r = 0; r < 4; r++) {
                    int row = mrow + g + (r & 1) * 8;
                    int col = ks * 8 + tg + (r >> 1) * 4;
                    tf32_split(As[cur][row * 20 + col], ah[mt][r], al[mt][r]);
                }
            }
            #pragma unroll
            for (int nt = 0; nt < 4; nt++) {
                int ncol = wn * 32 + nt * 8 + g;
                #pragma unroll
                for (int r = 0; r < 2; r++)
                    tf32_split(Bs[cur][(ks * 8 + tg + r * 4) * 72 + ncol],
                               bh[nt][r], bl[nt][r]);
            }
            #pragma unroll
            for (int mt = 0; mt < 2; mt++)
                #pragma unroll
                for (int nt = 0; nt < 4; nt++) {
                    mma8(c[mt][nt], ah[mt], bh[nt]);
                    mma8(c[mt][nt], ah[mt], bl[nt]);
                    mma8(c[mt][nt], al[mt], bh[nt]);
                }
        }
        if (i + 1 < NC) {
            int nxt = cur ^ 1;
            stage(i + 1, nxt);
            __syncthreads();
            cur = nxt;
        }
    }
    #pragma unroll
    for (int mt = 0; mt < 2; mt++) {
        int r0 = rowBase + wm * 32 + mt * 16 + g;
        #pragma unroll
        for (int nt = 0; nt < 4; nt++) {
            int col = colBase + wn * 32 + nt * 8 + 2 * tg;
            *(float2*)&out[(size_t)r0 * H2_D + col] =
                make_float2(c[mt][nt][0], c[mt][nt][1]);
            *(float2*)&out[(size_t)(r0 + 8) * H2_D + col] =
                make_float2(c[mt][nt][2], c[mt][nt][3]);
        }
    }
}

// ---------------- K5: column stats of h2 / h2w -------------------------------
__global__ void stats2_kernel() {
    int t = threadIdx.x;               // 256
    int row0 = blockIdx.x * 16;        // grid 256
    float s1 = 0, q1 = 0, s2 = 0, q2 = 0;
    #pragma unroll
    for (int r = 0; r < 16; r++) {
        int idx = (row0 + r) * H2_D + t;
        float v = g_h2[idx];  s1 += v; q1 += v * v;
        float w = g_h2w[idx]; s2 += w; q2 += w * w;
    }
    atomicAdd(&g_sum2[t], s1);        atomicAdd(&g_sq2[t], q1);
    atomicAdd(&g_sum2[256 + t], s2);  atomicAdd(&g_sq2[256 + t], q2);
}

// ---------------- K6: out = relu(BN(h2) + BN(h2w)) ---------------------------
__global__ void final_kernel(const float* __restrict__ g2, const float* __restrict__ be2,
                             const float* __restrict__ gw2, const float* __restrict__ bew2,
                             float* __restrict__ out) {
    int idx = blockIdx.x * blockDim.x + threadIdx.x;
    int c = idx & 255;
    float m0 = g_sum2[c] * (1.0f / 4096.0f);
    float v0 = g_sq2[c] * (1.0f / 4096.0f) - m0 * m0;
    float s0 = g2[c] * rsqrtf(v0 + EPS);
    float h0 = be2[c] - m0 * s0;
    float m1 = g_sum2[256 + c] * (1.0f / 4096.0f);
    float v1 = g_sq2[256 + c] * (1.0f / 4096.0f) - m1 * m1;
    float s1 = gw2[c] * rsqrtf(v1 + EPS);
    float h1 = bew2[c] - m1 * s1;
    float a = g_h2[idx]  * s0 + h0;
    float b = g_h2w[idx] * s1 + h1;
    out[idx] = fmaxf(a + b, 0.f);
}

// ---------------- launch -----------------------------------------------------
extern "C" void kernel_launch(void* const* d_in, const int* in_sizes, int n_in,
                              void* d_out, int out_size) {
    const float* x        = (const float*)d_in[0];
    const float* loc      = (const float*)d_in[1];
    const float* what_W1  = (const float*)d_in[2];
    const float* what_g1  = (const float*)d_in[4];
    const float* what_be1 = (const float*)d_in[5];
    const float* what_W2  = (const float*)d_in[6];
    const float* what_g2  = (const float*)d_in[8];
    const float* what_be2 = (const float*)d_in[9];
    const float* where_W1  = (const float*)d_in[10];
    const float* where_g1  = (const float*)d_in[12];
    const float* where_be1 = (const float*)d_in[13];
    const float* where_W2  = (const float*)d_in[14];
    const float* where_g2  = (const float*)d_in[16];
    const float* where_be2 = (const float*)d_in[17];
    float* out = (float*)d_out;

    foveate_kernel<<<B_SZ, 512>>>(x, loc);
    gemm1_kernel<<<dim3(B_SZ / 64, H1_D / 32), 128>>>(what_W1);
    stats1_kernel<<<256, 256>>>(loc, where_W1);
    gemm2_kernel<<<dim3(B_SZ / 128, H2_D / 64, 2), 256>>>(
        what_W2, where_W2, loc, where_W1,
        what_g1, what_be1, where_g1, where_be1);
    stats2_kernel<<<256, 256>>>();
    final_kernel<<<(B_SZ * H2_D) / 512, 512>>>(
        what_g2, what_be2, where_g2, where_be2, out);
}

// round 13
// speedup vs baseline: 2.2624x; 1.2197x over previous
#include <cuda_runtime.h>
#include <cstdint>

// Problem constants
#define B_SZ   4096
#define HH     128
#define PHI_D  784
#define H1_D   128
#define H2_D   256
#define L1W    57
#define L2W    29
#define EPS    1e-5f
#define NSPLIT 4
#define SPLIT_OFF (B_SZ * H1_D)

// ---------------- scratch ----------------------------------------------------
__device__ float g_phi[B_SZ * PHI_D];
__device__ float g_h1p[NSPLIT * B_SZ * H1_D];
__device__ float g_h1 [B_SZ * H1_D];
__device__ float g_h2 [B_SZ * H2_D];
__device__ float g_h2w[B_SZ * H2_D];
__device__ float g_sum1[2 * H1_D];
__device__ float g_sq1 [2 * H1_D];
__device__ float g_sum2[2 * H2_D];
__device__ float g_sq2 [2 * H2_D];

// ---------------- tf32 helpers -----------------------------------------------
__device__ __forceinline__ uint32_t tf32_of(float x) {
    uint32_t r;
    asm("cvt.rna.tf32.f32 %0, %1;" : "=r"(r) : "f"(x));
    return r;
}
__device__ __forceinline__ void tf32_split(float x, uint32_t& hi, uint32_t& lo) {
    hi = tf32_of(x);
    lo = tf32_of(x - __uint_as_float(hi));
}
__device__ __forceinline__ void mma8(float* c, const uint32_t* a, const uint32_t* b) {
    asm volatile(
        "mma.sync.aligned.m16n8k8.row.col.f32.tf32.tf32.f32 "
        "{%0,%1,%2,%3},{%4,%5,%6,%7},{%8,%9},{%0,%1,%2,%3};"
        : "+f"(c[0]), "+f"(c[1]), "+f"(c[2]), "+f"(c[3])
        : "r"(a[0]), "r"(a[1]), "r"(a[2]), "r"(a[3]), "r"(b[0]), "r"(b[1]));
}

// ---------------- K1: foveate via pyramid, low-smem --------------------------
// Patch p: size 14*2^p, window top-left 56-7*2^p: p0->49, p1->42, p2->28, p3->0
__global__ __launch_bounds__(512) void foveate_kernel(const float* __restrict__ x,
                                                      const float* __restrict__ loc) {
    __shared__ float L1[56 * L1W];
    __shared__ float L2[28 * L2W];
    __shared__ float ctr[14 * 15];

    int b = blockIdx.x;
    if (b == 0 && threadIdx.x < 256) {          // zero layer-1 stat accumulators
        g_sum1[threadIdx.x] = 0.f;
        g_sq1[threadIdx.x] = 0.f;
    }
    float lx = loc[2 * b + 0];
    float ly = loc[2 * b + 1];
    int cx = (int)(0.5f * ((lx + 1.0f) * 128.0f));
    int cy = (int)(0.5f * ((ly + 1.0f) * 128.0f));
    int wy0 = cy - 56, wx0 = cx - 56;
    const float* xb = x + (size_t)b * HH * HH;

    auto ld = [&](int gy, int gx) -> float {
        return (gy >= 0 && gy < HH && gx >= 0 && gx < HH) ? xb[gy * HH + gx] : 0.f;
    };

    for (int i = threadIdx.x; i < 56 * 56; i += 512) {
        int r = i / 56, c = i - r * 56;
        int gy = wy0 + 2 * r, gx = wx0 + 2 * c;
        L1[r * L1W + c] = (ld(gy, gx) + ld(gy, gx + 1))
                        + (ld(gy + 1, gx) + ld(gy + 1, gx + 1));
    }
    if (threadIdx.x < 196) {
        int i = threadIdx.x / 14, j = threadIdx.x - i * 14;
        ctr[i * 15 + j] = ld(wy0 + 49 + i, wx0 + 49 + j);
    }
    __syncthreads();

    for (int i = threadIdx.x; i < 28 * 28; i += 512) {
        int r = i / 28, c = i - r * 28;
        const float* a0 = &L1[(2 * r) * L1W + 2 * c];
        const float* a1 = a0 + L1W;
        L2[r * L2W + c] = (a0[0] + a0[1]) + (a1[0] + a1[1]);
    }
    __syncthreads();

    for (int o = threadIdx.x; o < PHI_D; o += 512) {
        int p   = o / 196;
        int rem = o - p * 196;
        int i   = rem / 14;
        int j   = rem - i * 14;
        float v;
        if (p == 0) {
            v = ctr[i * 15 + j];
        } else if (p == 1) {
            v = L1[(21 + i) * L1W + 21 + j] * 0.25f;
        } else if (p == 2) {
            v = L2[(7 + i) * L2W + 7 + j] * 0.0625f;
        } else {
            const float* q0 = &L2[(2 * i) * L2W + 2 * j];
            const float* q1 = q0 + L2W;
            v = ((q0[0] + q0[1]) + (q1[0] + q1[1])) * (1.0f / 64.0f);
        }
        g_phi[(size_t)b * PHI_D + o] = v;
    }
}

// ---------------- K2: GEMM1 split-K(4), 3xTF32 mma ---------------------------
// 128 threads (4 warps 2x2). BM=64, BN=32, BK=16. Warp tile 32x16. grid (64,4,4).
__global__ __launch_bounds__(128) void gemm1_kernel(const float* __restrict__ W) {
    __shared__ float As[2][64 * 20];   // [m][k] stride 20, conflict-free frags
    __shared__ float Bs[2][16 * 40];   // [k][n] stride 40, conflict-free frags

    int t = threadIdx.x;
    int lane = t & 31, warp = t >> 5;
    int wm = warp >> 1, wn = warp & 1;
    int g = lane >> 2, tg = lane & 3;
    int rowBase = blockIdx.x * 64;
    int colBase = blockIdx.y * 32;
    int s = blockIdx.z;
    int t0 = (s == 0) ? 0 : 13 + 12 * (s - 1);   // 49 tiles: [13,12,12,12]
    int nt = (s == 0) ? 13 : 12;
    float* out = g_h1p + (size_t)s * SPLIT_OFF;

    int ar = t >> 1, ako = (t & 1) * 8;
    int bkr = t >> 3, bcc = (t & 7) * 4;

    float4 pa0, pa1, pb;
    float c[2][2][4] = {};

    auto fetch = [&](int kt) {
        const float* ap = &g_phi[(size_t)(rowBase + ar) * PHI_D + kt * 16 + ako];
        pa0 = *(const float4*)ap;
        pa1 = *(const float4*)(ap + 4);
        pb  = *(const float4*)&W[(size_t)(kt * 16 + bkr) * H1_D + colBase + bcc];
    };
    auto stage = [&](int buf) {
        float* a = &As[buf][ar * 20 + ako];
        *(float4*)a       = pa0;
        *(float4*)(a + 4) = pa1;
        *(float4*)&Bs[buf][bkr * 40 + bcc] = pb;
    };

    fetch(t0); stage(0); __syncthreads();
    int cur = 0;
    for (int i = 0; i < nt; i++) {
        if (i + 1 < nt) fetch(t0 + i + 1);
        #pragma unroll
        for (int ks = 0; ks < 2; ks++) {
            uint32_t ah[2][4], al[2][4], bh[2][2], bl[2][2];
            #pragma unroll
            for (int mt = 0; mt < 2; mt++) {
                int mrow = wm * 32 + mt * 16;
                #pragma unroll
                for (int r = 0; r < 4; r++) {
                    int row = mrow + g + (r & 1) * 8;
                    int col = ks * 8 + tg + (r >> 1) * 4;
                    tf32_split(As[cur][row * 20 + col], ah[mt][r], al[mt][r]);
                }
            }
            #pragma unroll
            for (int nt2 = 0; nt2 < 2; nt2++) {
                int ncol = wn * 16 + nt2 * 8 + g;
                #pragma unroll
                for (int r = 0; r < 2; r++)
                    tf32_split(Bs[cur][(ks * 8 + tg + r * 4) * 40 + ncol],
                               bh[nt2][r], bl[nt2][r]);
            }
            #pragma unroll
            for (int mt = 0; mt < 2; mt++)
                #pragma unroll
                for (int nt2 = 0; nt2 < 2; nt2++) {
                    mma8(c[mt][nt2], ah[mt], bh[nt2]);
                    mma8(c[mt][nt2], ah[mt], bl[nt2]);
                    mma8(c[mt][nt2], al[mt], bh[nt2]);
                }
        }
        if (i + 1 < nt) {
            int nxt = cur ^ 1;
            stage(nxt);
            __syncthreads();
            cur = nxt;
        }
    }
    #pragma unroll
    for (int mt = 0; mt < 2; mt++) {
        int r0 = rowBase + wm * 32 + mt * 16 + g;
        #pragma unroll
        for (int nt2 = 0; nt2 < 2; nt2++) {
            int col = colBase + wn * 16 + nt2 * 8 + 2 * tg;
            *(float2*)&out[(size_t)r0 * H1_D + col] =
                make_float2(c[mt][nt2][0], c[mt][nt2][1]);
            *(float2*)&out[(size_t)(r0 + 8) * H1_D + col] =
                make_float2(c[mt][nt2][2], c[mt][nt2][3]);
        }
    }
}

// ---------------- K3: merge split-K partials -> g_h1 + column stats ----------
__global__ void stats1_kernel(const float* __restrict__ loc,
                              const float* __restrict__ Ww1) {
    int t = threadIdx.x;
    int row0 = blockIdx.x * 16;    // grid 256
    int col = t & 127;
    int rh = t >> 7;

    if (blockIdx.x == 0 && t < 256) {
        g_sum2[t] = 0.f; g_sum2[t + 256] = 0.f;
        g_sq2[t] = 0.f;  g_sq2[t + 256] = 0.f;
    }

    float s = 0.f, q = 0.f;
    #pragma unroll
    for (int r = 0; r < 16; r += 2) {
        int idx = (row0 + r + rh) * H1_D + col;
        float v = 0.f;
        #pragma unroll
        for (int k = 0; k < NSPLIT; k++) v += g_h1p[idx + k * SPLIT_OFF];
        g_h1[idx] = v;
        s += v; q += v * v;
    }
    atomicAdd(&g_sum1[col], s); atomicAdd(&g_sq1[col], q);

    float w0 = Ww1[col], w1 = Ww1[H1_D + col];
    s = 0.f; q = 0.f;
    #pragma unroll
    for (int r = 0; r < 16; r += 2) {
        int b = row0 + r + rh;
        float v = loc[2 * b] * w0 + loc[2 * b + 1] * w1;
        s += v; q += v * v;
    }
    atomicAdd(&g_sum1[H1_D + col], s); atomicAdd(&g_sq1[H1_D + col], q);
}

// ---------------- K4: GEMM2 both paths, 3xTF32 mma, BN+relu at staging -------
// 256 threads (8 warps 4x2). BM=128, BN=64, BK=16. Warp tile 32x32.
__global__ __launch_bounds__(256) void gemm2_kernel(
        const float* __restrict__ W2,     // (128,256)
        const float* __restrict__ Ww2,    // (128,256)
        const float* __restrict__ loc,
        const float* __restrict__ Ww1,    // (2,128)
        const float* __restrict__ g1, const float* __restrict__ be1,
        const float* __restrict__ gw1, const float* __restrict__ bew1) {
    __shared__ float As[2][128 * 20];    // 20.5KB
    __shared__ float Bs[2][16 * 72];     // 9.2KB
    __shared__ float scs[H1_D], shs[H1_D];

    int path = blockIdx.z;
    const float* W   = path ? Ww2  : W2;
    float*       out = path ? g_h2w : g_h2;
    int soff = path * H1_D;

    int t = threadIdx.x;
    int lane = t & 31, warp = t >> 5;
    int wm = warp >> 1, wn = warp & 1;
    int g = lane >> 2, tg = lane & 3;
    int rowBase = blockIdx.x * 128;
    int colBase = blockIdx.y * 64;

    if (t < H1_D) {
        float mean = g_sum1[soff + t] * (1.0f / 4096.0f);
        float var  = g_sq1[soff + t] * (1.0f / 4096.0f) - mean * mean;
        float gam = path ? gw1[t] : g1[t];
        float bet = path ? bew1[t] : be1[t];
        float sc = gam * rsqrtf(var + EPS);
        scs[t] = sc;
        shs[t] = bet - mean * sc;
    }

    int ar = t >> 1, ako = (t & 1) * 8;
    int bkr = t >> 4, bcc = (t & 15) * 4;
    float lx = 0.f, ly = 0.f;
    if (path) { lx = loc[2 * (rowBase + ar)]; ly = loc[2 * (rowBase + ar) + 1]; }

    float4 pa[2], pb;
    float c[2][4][4] = {};

    auto fetch = [&](int kt) {
        int k0 = kt * 16 + ako;
        if (path == 0) {
            const float* ap = &g_h1[(size_t)(rowBase + ar) * H1_D + k0];
            pa[0] = *(const float4*)ap;
            pa[1] = *(const float4*)(ap + 4);
        } else {
            #pragma unroll
            for (int j = 0; j < 2; j++) {
                float4 w0 = *(const float4*)&Ww1[k0 + j * 4];
                float4 w1 = *(const float4*)&Ww1[H1_D + k0 + j * 4];
                pa[j] = make_float4(lx * w0.x + ly * w1.x, lx * w0.y + ly * w1.y,
                                    lx * w0.z + ly * w1.z, lx * w0.w + ly * w1.w);
            }
        }
        pb = *(const float4*)&W[(size_t)(kt * 16 + bkr) * H2_D + colBase + bcc];
    };
    auto stage = [&](int kt, int buf) {
        int k0 = kt * 16 + ako;
        float* a = &As[buf][ar * 20 + ako];
        #pragma unroll
        for (int j = 0; j < 2; j++) {
            float4 v = pa[j];
            float4 sc4 = *(const float4*)&scs[k0 + j * 4];
            float4 sh4 = *(const float4*)&shs[k0 + j * 4];
            float4 r;
            r.x = fmaxf(v.x * sc4.x + sh4.x, 0.f);
            r.y = fmaxf(v.y * sc4.y + sh4.y, 0.f);
            r.z = fmaxf(v.z * sc4.z + sh4.z, 0.f);
            r.w = fmaxf(v.w * sc4.w + sh4.w, 0.f);
            *(float4*)(a + j * 4) = r;
        }
        *(float4*)&Bs[buf][bkr * 72 + bcc] = pb;
    };

    fetch(0);
    __syncthreads();
    stage(0, 0);
    __syncthreads();
    int cur = 0;
    const int NC = H1_D / 16;   // 8
    for (int i = 0; i < NC; i++) {
        if (i + 1 < NC) fetch(i + 1);
        #pragma unroll
        for (int ks = 0; ks < 2; ks++) {
            uint32_t ah[2][4], al[2][4], bh[4][2], bl[4][2];
            #pragma unroll
            for (int mt = 0; mt < 2; mt++) {
                int mrow = wm * 32 + mt * 16;
                #pragma unroll
                for (int r = 0; r < 4; r++) {
                    int row = mrow + g + (r & 1) * 8;
                    int col = ks * 8 + tg + (r >> 1) * 4;
                    tf32_split(As[cur][row * 20 + col], ah[mt][r], al[mt][r]);
                }
            }
            #pragma unroll
            for (int nt = 0; nt < 4; nt++) {
                int ncol = wn * 32 + nt * 8 + g;
                #pragma unroll
                for (int r = 0; r < 2; r++)
                    tf32_split(Bs[cur][(ks * 8 + tg + r * 4) * 72 + ncol],
                               bh[nt][r], bl[nt][r]);
            }
            #pragma unroll
            for (int mt = 0; mt < 2; mt++)
                #pragma unroll
                for (int nt = 0; nt < 4; nt++) {
                    mma8(c[mt][nt], ah[mt], bh[nt]);
                    mma8(c[mt][nt], ah[mt], bl[nt]);
                    mma8(c[mt][nt], al[mt], bh[nt]);
                }
        }
        if (i + 1 < NC) {
            int nxt = cur ^ 1;
            stage(i + 1, nxt);
            __syncthreads();
            cur = nxt;
        }
    }
    #pragma unroll
    for (int mt = 0; mt < 2; mt++) {
        int r0 = rowBase + wm * 32 + mt * 16 + g;
        #pragma unroll
        for (int nt = 0; nt < 4; nt++) {
            int col = colBase + wn * 32 + nt * 8 + 2 * tg;
            *(float2*)&out[(size_t)r0 * H2_D + col] =
                make_float2(c[mt][nt][0], c[mt][nt][1]);
            *(float2*)&out[(size_t)(r0 + 8) * H2_D + col] =
                make_float2(c[mt][nt][2], c[mt][nt][3]);
        }
    }
}

// ---------------- K5: column stats of h2 / h2w -------------------------------
__global__ void stats2_kernel() {
    int t = threadIdx.x;               // 256
    int row0 = blockIdx.x * 16;        // grid 256
    float s1 = 0, q1 = 0, s2 = 0, q2 = 0;
    #pragma unroll
    for (int r = 0; r < 16; r++) {
        int idx = (row0 + r) * H2_D + t;
        float v = g_h2[idx];  s1 += v; q1 += v * v;
        float w = g_h2w[idx]; s2 += w; q2 += w * w;
    }
    atomicAdd(&g_sum2[t], s1);        atomicAdd(&g_sq2[t], q1);
    atomicAdd(&g_sum2[256 + t], s2);  atomicAdd(&g_sq2[256 + t], q2);
}

// ---------------- K6: out = relu(BN(h2) + BN(h2w)) ---------------------------
__global__ void final_kernel(const float* __restrict__ g2, const float* __restrict__ be2,
                             const float* __restrict__ gw2, const float* __restrict__ bew2,
                             float* __restrict__ out) {
    int idx = blockIdx.x * blockDim.x + threadIdx.x;
    int c = idx & 255;
    float m0 = g_sum2[c] * (1.0f / 4096.0f);
    float v0 = g_sq2[c] * (1.0f / 4096.0f) - m0 * m0;
    float s0 = g2[c] * rsqrtf(v0 + EPS);
    float h0 = be2[c] - m0 * s0;
    float m1 = g_sum2[256 + c] * (1.0f / 4096.0f);
    float v1 = g_sq2[256 + c] * (1.0f / 4096.0f) - m1 * m1;
    float s1 = gw2[c] * rsqrtf(v1 + EPS);
    float h1 = bew2[c] - m1 * s1;
    float a = g_h2[idx]  * s0 + h0;
    float b = g_h2w[idx] * s1 + h1;
    out[idx] = fmaxf(a + b, 0.f);
}

// ---------------- launch -----------------------------------------------------
extern "C" void kernel_launch(void* const* d_in, const int* in_sizes, int n_in,
                              void* d_out, int out_size) {
    const float* x        = (const float*)d_in[0];
    const float* loc      = (const float*)d_in[1];
    const float* what_W1  = (const float*)d_in[2];
    const float* what_g1  = (const float*)d_in[4];
    const float* what_be1 = (const float*)d_in[5];
    const float* what_W2  = (const float*)d_in[6];
    const float* what_g2  = (const float*)d_in[8];
    const float* what_be2 = (const float*)d_in[9];
    const float* where_W1  = (const float*)d_in[10];
    const float* where_g1  = (const float*)d_in[12];
    const float* where_be1 = (const float*)d_in[13];
    const float* where_W2  = (const float*)d_in[14];
    const float* where_g2  = (const float*)d_in[16];
    const float* where_be2 = (const float*)d_in[17];
    float* out = (float*)d_out;

    foveate_kernel<<<B_SZ, 512>>>(x, loc);
    gemm1_kernel<<<dim3(B_SZ / 64, H1_D / 32, NSPLIT), 128>>>(what_W1);
    stats1_kernel<<<256, 256>>>(loc, where_W1);
    gemm2_kernel<<<dim3(B_SZ / 128, H2_D / 64, 2), 256>>>(
        what_W2, where_W2, loc, where_W1,
        what_g1, what_be1, where_g1, where_be1);
    stats2_kernel<<<256, 256>>>();
    final_kernel<<<(B_SZ * H2_D) / 512, 512>>>(
        what_g2, what_be2, where_g2, where_be2, out);
}

// round 14
// speedup vs baseline: 2.2906x; 1.0124x over previous
#include <cuda_runtime.h>
#include <cstdint>

// Problem constants
#define B_SZ   4096
#define HH     128
#define PHI_D  784
#define H1_D   128
#define H2_D   256
#define L1W    57
#define L2W    29
#define EPS    1e-5f
#define NSPLIT 4
#define SPLIT_OFF (B_SZ * H1_D)

// ---------------- scratch ----------------------------------------------------
__device__ float g_phi[B_SZ * PHI_D];
__device__ float g_h1p[NSPLIT * B_SZ * H1_D];
__device__ float g_h1 [B_SZ * H1_D];
__device__ float g_h2 [B_SZ * H2_D];
__device__ float g_h2w[B_SZ * H2_D];
__device__ float g_sum1[2 * H1_D];
__device__ float g_sq1 [2 * H1_D];
__device__ float g_sum2[2 * H2_D];
__device__ float g_sq2 [2 * H2_D];

// ---------------- tf32 helpers -----------------------------------------------
__device__ __forceinline__ uint32_t tf32_of(float x) {
    uint32_t r;
    asm("cvt.rna.tf32.f32 %0, %1;" : "=r"(r) : "f"(x));
    return r;
}
__device__ __forceinline__ void tf32_split(float x, uint32_t& hi, uint32_t& lo) {
    hi = tf32_of(x);
    lo = tf32_of(x - __uint_as_float(hi));
}
__device__ __forceinline__ void mma8(float* c, const uint32_t* a, const uint32_t* b) {
    asm volatile(
        "mma.sync.aligned.m16n8k8.row.col.f32.tf32.tf32.f32 "
        "{%0,%1,%2,%3},{%4,%5,%6,%7},{%8,%9},{%0,%1,%2,%3};"
        : "+f"(c[0]), "+f"(c[1]), "+f"(c[2]), "+f"(c[3])
        : "r"(a[0]), "r"(a[1]), "r"(a[2]), "r"(a[3]), "r"(b[0]), "r"(b[1]));
}

// ---------------- K1: foveate via pyramid --------------------------------------
// Patch p: size 14*2^p, window top-left 56-7*2^p: p0->49, p1->42, p2->28, p3->0
__global__ __launch_bounds__(512) void foveate_kernel(const float* __restrict__ x,
                                                      const float* __restrict__ loc) {
    __shared__ float L1[56 * L1W];
    __shared__ float L2[28 * L2W];
    __shared__ float ctr[14 * 15];

    int b = blockIdx.x;
    int t = threadIdx.x;
    if (b == 0 && t < 256) {          // zero layer-1 stat accumulators
        g_sum1[t] = 0.f;
        g_sq1[t] = 0.f;
    }
    float lx = loc[2 * b + 0];
    float ly = loc[2 * b + 1];
    int cx = (int)(0.5f * ((lx + 1.0f) * 128.0f));
    int cy = (int)(0.5f * ((ly + 1.0f) * 128.0f));
    int wy0 = cy - 56, wx0 = cx - 56;
    const float* xb = x + (size_t)b * HH * HH;

    // L1 from global: c = t&63 (active <56), rows r0 + 8k. No divisions.
    {
        int c  = t & 63;
        int r0 = t >> 6;          // 0..7
        if (c < 56) {
            int gx0 = wx0 + 2 * c, gx1 = gx0 + 1;
            bool cok0 = (unsigned)gx0 < 128u;
            bool cok1 = (unsigned)gx1 < 128u;
            #pragma unroll
            for (int rr = 0; rr < 7; rr++) {
                int r = r0 + rr * 8;
                int gy0 = wy0 + 2 * r, gy1 = gy0 + 1;
                bool rok0 = (unsigned)gy0 < 128u;
                bool rok1 = (unsigned)gy1 < 128u;
                const float* p0 = xb + gy0 * HH;
                const float* p1 = xb + gy1 * HH;
                float v = 0.f;
                if (rok0 & cok0) v += p0[gx0];
                if (rok0 & cok1) v += p0[gx1];
                if (rok1 & cok0) v += p1[gx0];
                if (rok1 & cok1) v += p1[gx1];
                L1[r * L1W + c] = v;
            }
        }
    }
    // center 14x14 (patch0) raw pixels
    if (t < 196) {
        int i = t / 14, j = t - i * 14;
        int gy = wy0 + 49 + i, gx = wx0 + 49 + j;
        float v = 0.f;
        if (((unsigned)gy < 128u) & ((unsigned)gx < 128u)) v = xb[gy * HH + gx];
        ctr[i * 15 + j] = v;
    }
    __syncthreads();

    for (int i = t; i < 28 * 28; i += 512) {
        int r = i / 28, c = i - r * 28;
        const float* a0 = &L1[(2 * r) * L1W + 2 * c];
        const float* a1 = a0 + L1W;
        L2[r * L2W + c] = (a0[0] + a0[1]) + (a1[0] + a1[1]);
    }
    __syncthreads();

    for (int o = t; o < PHI_D; o += 512) {
        int p   = o / 196;
        int rem = o - p * 196;
        int i   = rem / 14;
        int j   = rem - i * 14;
        float v;
        if (p == 0) {
            v = ctr[i * 15 + j];
        } else if (p == 1) {
            v = L1[(21 + i) * L1W + 21 + j] * 0.25f;
        } else if (p == 2) {
            v = L2[(7 + i) * L2W + 7 + j] * 0.0625f;
        } else {
            const float* q0 = &L2[(2 * i) * L2W + 2 * j];
            const float* q1 = q0 + L2W;
            v = ((q0[0] + q0[1]) + (q1[0] + q1[1])) * (1.0f / 64.0f);
        }
        g_phi[(size_t)b * PHI_D + o] = v;
    }
}

// ---------------- K2: GEMM1 split-K(4), 3xTF32 mma ---------------------------
// 128 threads (4 warps 2x2). BM=64, BN=32, BK=16. Warp tile 32x16. grid (64,4,4).
__global__ __launch_bounds__(128) void gemm1_kernel(const float* __restrict__ W) {
    __shared__ float As[2][64 * 20];
    __shared__ float Bs[2][16 * 40];

    int t = threadIdx.x;
    int lane = t & 31, warp = t >> 5;
    int wm = warp >> 1, wn = warp & 1;
    int g = lane >> 2, tg = lane & 3;
    int rowBase = blockIdx.x * 64;
    int colBase = blockIdx.y * 32;
    int s = blockIdx.z;
    int t0 = (s == 0) ? 0 : 13 + 12 * (s - 1);   // 49 tiles: [13,12,12,12]
    int nt = (s == 0) ? 13 : 12;
    float* out = g_h1p + (size_t)s * SPLIT_OFF;

    int ar = t >> 1, ako = (t & 1) * 8;
    int bkr = t >> 3, bcc = (t & 7) * 4;

    float4 pa0, pa1, pb;
    float c[2][2][4] = {};

    auto fetch = [&](int kt) {
        const float* ap = &g_phi[(size_t)(rowBase + ar) * PHI_D + kt * 16 + ako];
        pa0 = *(const float4*)ap;
        pa1 = *(const float4*)(ap + 4);
        pb  = *(const float4*)&W[(size_t)(kt * 16 + bkr) * H1_D + colBase + bcc];
    };
    auto stage = [&](int buf) {
        float* a = &As[buf][ar * 20 + ako];
        *(float4*)a       = pa0;
        *(float4*)(a + 4) = pa1;
        *(float4*)&Bs[buf][bkr * 40 + bcc] = pb;
    };

    fetch(t0); stage(0); __syncthreads();
    int cur = 0;
    for (int i = 0; i < nt; i++) {
        if (i + 1 < nt) fetch(t0 + i + 1);
        #pragma unroll
        for (int ks = 0; ks < 2; ks++) {
            uint32_t ah[2][4], al[2][4], bh[2][2], bl[2][2];
            #pragma unroll
            for (int mt = 0; mt < 2; mt++) {
                int mrow = wm * 32 + mt * 16;
                #pragma unroll
                for (int r = 0; r < 4; r++) {
                    int row = mrow + g + (r & 1) * 8;
                    int col = ks * 8 + tg + (r >> 1) * 4;
                    tf32_split(As[cur][row * 20 + col], ah[mt][r], al[mt][r]);
                }
            }
            #pragma unroll
            for (int nt2 = 0; nt2 < 2; nt2++) {
                int ncol = wn * 16 + nt2 * 8 + g;
                #pragma unroll
                for (int r = 0; r < 2; r++)
                    tf32_split(Bs[cur][(ks * 8 + tg + r * 4) * 40 + ncol],
                               bh[nt2][r], bl[nt2][r]);
            }
            #pragma unroll
            for (int mt = 0; mt < 2; mt++)
                #pragma unroll
                for (int nt2 = 0; nt2 < 2; nt2++) {
                    mma8(c[mt][nt2], ah[mt], bh[nt2]);
                    mma8(c[mt][nt2], ah[mt], bl[nt2]);
                    mma8(c[mt][nt2], al[mt], bh[nt2]);
                }
        }
        if (i + 1 < nt) {
            int nxt = cur ^ 1;
            stage(nxt);
            __syncthreads();
            cur = nxt;
        }
    }
    #pragma unroll
    for (int mt = 0; mt < 2; mt++) {
        int r0 = rowBase + wm * 32 + mt * 16 + g;
        #pragma unroll
        for (int nt2 = 0; nt2 < 2; nt2++) {
            int col = colBase + wn * 16 + nt2 * 8 + 2 * tg;
            *(float2*)&out[(size_t)r0 * H1_D + col] =
                make_float2(c[mt][nt2][0], c[mt][nt2][1]);
            *(float2*)&out[(size_t)(r0 + 8) * H1_D + col] =
                make_float2(c[mt][nt2][2], c[mt][nt2][3]);
        }
    }
}

// ---------------- K3: merge split-K partials -> g_h1 + column stats ----------
__global__ void stats1_kernel(const float* __restrict__ loc,
                              const float* __restrict__ Ww1) {
    int t = threadIdx.x;
    int row0 = blockIdx.x * 16;    // grid 256
    int col = t & 127;
    int rh = t >> 7;

    if (blockIdx.x == 0 && t < 256) {
        g_sum2[t] = 0.f; g_sum2[t + 256] = 0.f;
        g_sq2[t] = 0.f;  g_sq2[t + 256] = 0.f;
    }

    float s = 0.f, q = 0.f;
    #pragma unroll
    for (int r = 0; r < 16; r += 2) {
        int idx = (row0 + r + rh) * H1_D + col;
        float v = 0.f;
        #pragma unroll
        for (int k = 0; k < NSPLIT; k++) v += g_h1p[idx + k * SPLIT_OFF];
        g_h1[idx] = v;
        s += v; q += v * v;
    }
    atomicAdd(&g_sum1[col], s); atomicAdd(&g_sq1[col], q);

    float w0 = Ww1[col], w1 = Ww1[H1_D + col];
    s = 0.f; q = 0.f;
    #pragma unroll
    for (int r = 0; r < 16; r += 2) {
        int b = row0 + r + rh;
        float v = loc[2 * b] * w0 + loc[2 * b + 1] * w1;
        s += v; q += v * v;
    }
    atomicAdd(&g_sum1[H1_D + col], s); atomicAdd(&g_sq1[H1_D + col], q);
}

// ---------------- K4: GEMM2 both paths, 3xTF32 mma; BN+relu; stats2 fused ----
// 256 threads (8 warps 4x2). BM=128, BN=64, BK=16. Warp tile 32x32.
__global__ __launch_bounds__(256) void gemm2_kernel(
        const float* __restrict__ W2,     // (128,256)
        const float* __restrict__ Ww2,    // (128,256)
        const float* __restrict__ loc,
        const float* __restrict__ Ww1,    // (2,128)
        const float* __restrict__ g1, const float* __restrict__ be1,
        const float* __restrict__ gw1, const float* __restrict__ bew1) {
    __shared__ float As[2][128 * 20];    // 20.5KB
    __shared__ float Bs[2][16 * 72];     // 9.2KB
    __shared__ float scs[H1_D], shs[H1_D];
    __shared__ float2 red[8][64];        // 4KB: per-warp column partials

    int path = blockIdx.z;
    const float* W   = path ? Ww2  : W2;
    float*       out = path ? g_h2w : g_h2;
    int soff = path * H1_D;

    int t = threadIdx.x;
    int lane = t & 31, warp = t >> 5;
    int wm = warp >> 1, wn = warp & 1;
    int g = lane >> 2, tg = lane & 3;
    int rowBase = blockIdx.x * 128;
    int colBase = blockIdx.y * 64;

    if (t < H1_D) {
        float mean = g_sum1[soff + t] * (1.0f / 4096.0f);
        float var  = g_sq1[soff + t] * (1.0f / 4096.0f) - mean * mean;
        float gam = path ? gw1[t] : g1[t];
        float bet = path ? bew1[t] : be1[t];
        float sc = gam * rsqrtf(var + EPS);
        scs[t] = sc;
        shs[t] = bet - mean * sc;
    }

    int ar = t >> 1, ako = (t & 1) * 8;
    int bkr = t >> 4, bcc = (t & 15) * 4;
    float lx = 0.f, ly = 0.f;
    if (path) { lx = loc[2 * (rowBase + ar)]; ly = loc[2 * (rowBase + ar) + 1]; }

    float4 pa[2], pb;
    float c[2][4][4] = {};

    auto fetch = [&](int kt) {
        int k0 = kt * 16 + ako;
        if (path == 0) {
            const float* ap = &g_h1[(size_t)(rowBase + ar) * H1_D + k0];
            pa[0] = *(const float4*)ap;
            pa[1] = *(const float4*)(ap + 4);
        } else {
            #pragma unroll
            for (int j = 0; j < 2; j++) {
                float4 w0 = *(const float4*)&Ww1[k0 + j * 4];
                float4 w1 = *(const float4*)&Ww1[H1_D + k0 + j * 4];
                pa[j] = make_float4(lx * w0.x + ly * w1.x, lx * w0.y + ly * w1.y,
                                    lx * w0.z + ly * w1.z, lx * w0.w + ly * w1.w);
            }
        }
        pb = *(const float4*)&W[(size_t)(kt * 16 + bkr) * H2_D + colBase + bcc];
    };
    auto stage = [&](int kt, int buf) {
        int k0 = kt * 16 + ako;
        float* a = &As[buf][ar * 20 + ako];
        #pragma unroll
        for (int j = 0; j < 2; j++) {
            float4 v = pa[j];
            float4 sc4 = *(const float4*)&scs[k0 + j * 4];
            float4 sh4 = *(const float4*)&shs[k0 + j * 4];
            float4 r;
            r.x = fmaxf(v.x * sc4.x + sh4.x, 0.f);
            r.y = fmaxf(v.y * sc4.y + sh4.y, 0.f);
            r.z = fmaxf(v.z * sc4.z + sh4.z, 0.f);
            r.w = fmaxf(v.w * sc4.w + sh4.w, 0.f);
            *(float4*)(a + j * 4) = r;
        }
        *(float4*)&Bs[buf][bkr * 72 + bcc] = pb;
    };

    fetch(0);
    __syncthreads();
    stage(0, 0);
    __syncthreads();
    int cur = 0;
    const int NC = H1_D / 16;   // 8
    for (int i = 0; i < NC; i++) {
        if (i + 1 < NC) fetch(i + 1);
        #pragma unroll
        for (int ks = 0; ks < 2; ks++) {
            uint32_t ah[2][4], al[2][4], bh[4][2], bl[4][2];
            #pragma unroll
            for (int mt = 0; mt < 2; mt++) {
                int mrow = wm * 32 + mt * 16;
                #pragma unroll
                for (int r = 0; r < 4; r++) {
                    int row = mrow + g + (r & 1) * 8;
                    int col = ks * 8 + tg + (r >> 1) * 4;
                    tf32_split(As[cur][row * 20 + col], ah[mt][r], al[mt][r]);
                }
            }
            #pragma unroll
            for (int nt = 0; nt < 4; nt++) {
                int ncol = wn * 32 + nt * 8 + g;
                #pragma unroll
                for (int r = 0; r < 2; r++)
                    tf32_split(Bs[cur][(ks * 8 + tg + r * 4) * 72 + ncol],
                               bh[nt][r], bl[nt][r]);
            }
            #pragma unroll
            for (int mt = 0; mt < 2; mt++)
                #pragma unroll
                for (int nt = 0; nt < 4; nt++) {
                    mma8(c[mt][nt], ah[mt], bh[nt]);
                    mma8(c[mt][nt], ah[mt], bl[nt]);
                    mma8(c[mt][nt], al[mt], bh[nt]);
                }
        }
        if (i + 1 < NC) {
            int nxt = cur ^ 1;
            stage(i + 1, nxt);
            __syncthreads();
            cur = nxt;
        }
    }
    #pragma unroll
    for (int mt = 0; mt < 2; mt++) {
        int r0 = rowBase + wm * 32 + mt * 16 + g;
        #pragma unroll
        for (int nt = 0; nt < 4; nt++) {
            int col = colBase + wn * 32 + nt * 8 + 2 * tg;
            *(float2*)&out[(size_t)r0 * H2_D + col] =
                make_float2(c[mt][nt][0], c[mt][nt][1]);
            *(float2*)&out[(size_t)(r0 + 8) * H2_D + col] =
                make_float2(c[mt][nt][2], c[mt][nt][3]);
        }
    }

    // fused column stats: xor-shuffle across g-groups, per-warp red[], atomics.
    #pragma unroll
    for (int nt = 0; nt < 4; nt++) {
        #pragma unroll
        for (int j = 0; j < 2; j++) {
            float a0 = c[0][nt][j],     a1 = c[0][nt][j + 2];
            float a2 = c[1][nt][j],     a3 = c[1][nt][j + 2];
            float s = a0 + a1 + a2 + a3;
            float q = a0 * a0 + a1 * a1 + a2 * a2 + a3 * a3;
            s += __shfl_xor_sync(0xffffffff, s, 4);
            q += __shfl_xor_sync(0xffffffff, q, 4);
            s += __shfl_xor_sync(0xffffffff, s, 8);
            q += __shfl_xor_sync(0xffffffff, q, 8);
            s += __shfl_xor_sync(0xffffffff, s, 16);
            q += __shfl_xor_sync(0xffffffff, q, 16);
            if (g == 0)
                red[warp][wn * 32 + nt * 8 + 2 * tg + j] = make_float2(s, q);
        }
    }
    __syncthreads();
    if (t < 64) {
        int w0 = (t >= 32) ? 1 : 0;
        float s = 0.f, q = 0.f;
        #pragma unroll
        for (int k = 0; k < 4; k++) {
            float2 v = red[w0 + 2 * k][t];
            s += v.x; q += v.y;
        }
        int col = path * H2_D + colBase + t;
        atomicAdd(&g_sum2[col], s);
        atomicAdd(&g_sq2[col], q);
    }
}

// ---------------- K6: out = relu(BN(h2) + BN(h2w)) ---------------------------
__global__ void final_kernel(const float* __restrict__ g2, const float* __restrict__ be2,
                             const float* __restrict__ gw2, const float* __restrict__ bew2,
                             float* __restrict__ out) {
    int idx = blockIdx.x * blockDim.x + threadIdx.x;
    int c = idx & 255;
    float m0 = g_sum2[c] * (1.0f / 4096.0f);
    float v0 = g_sq2[c] * (1.0f / 4096.0f) - m0 * m0;
    float s0 = g2[c] * rsqrtf(v0 + EPS);
    float h0 = be2[c] - m0 * s0;
    float m1 = g_sum2[256 + c] * (1.0f / 4096.0f);
    float v1 = g_sq2[256 + c] * (1.0f / 4096.0f) - m1 * m1;
    float s1 = gw2[c] * rsqrtf(v1 + EPS);
    float h1 = bew2[c] - m1 * s1;
    float a = g_h2[idx]  * s0 + h0;
    float b = g_h2w[idx] * s1 + h1;
    out[idx] = fmaxf(a + b, 0.f);
}

// ---------------- launch -----------------------------------------------------
extern "C" void kernel_launch(void* const* d_in, const int* in_sizes, int n_in,
                              void* d_out, int out_size) {
    const float* x        = (const float*)d_in[0];
    const float* loc      = (const float*)d_in[1];
    const float* what_W1  = (const float*)d_in[2];
    const float* what_g1  = (const float*)d_in[4];
    const float* what_be1 = (const float*)d_in[5];
    const float* what_W2  = (const float*)d_in[6];
    const float* what_g2  = (const float*)d_in[8];
    const float* what_be2 = (const float*)d_in[9];
    const float* where_W1  = (const float*)d_in[10];
    const float* where_g1  = (const float*)d_in[12];
    const float* where_be1 = (const float*)d_in[13];
    const float* where_W2  = (const float*)d_in[14];
    const float* where_g2  = (const float*)d_in[16];
    const float* where_be2 = (const float*)d_in[17];
    float* out = (float*)d_out;

    foveate_kernel<<<B_SZ, 512>>>(x, loc);
    gemm1_kernel<<<dim3(B_SZ / 64, H1_D / 32, NSPLIT), 128>>>(what_W1);
    stats1_kernel<<<256, 256>>>(loc, where_W1);
    gemm2_kernel<<<dim3(B_SZ / 128, H2_D / 64, 2), 256>>>(
        what_W2, where_W2, loc, where_W1,
        what_g1, what_be1, where_g1, where_be1);
    final_kernel<<<(B_SZ * H2_D) / 512, 512>>>(
        what_g2, what_be2, where_g2, where_be2, out);
}

// round 16
// speedup vs baseline: 2.4225x; 1.0576x over previous
#include <cuda_runtime.h>
#include <cstdint>

// Problem constants
#define B_SZ   4096
#define HH     128
#define PHI_D  784
#define H1_D   128
#define H2_D   256
#define L1W    57
#define L2W    29
#define EPS    1e-5f
#define NSPLIT 4
#define SPLIT_OFF (B_SZ * H1_D)

// ---------------- scratch ----------------------------------------------------
__device__ float g_phi[B_SZ * PHI_D];
__device__ float g_h1p[NSPLIT * B_SZ * H1_D];
__device__ float g_h1 [B_SZ * H1_D];
__device__ float g_h2 [B_SZ * H2_D];
__device__ float g_h2w[B_SZ * H2_D];
__device__ float g_sum1[2 * H1_D];
__device__ float g_sq1 [2 * H1_D];
__device__ float g_sum2[2 * H2_D];
__device__ float g_sq2 [2 * H2_D];

// ---------------- tf32 helpers -----------------------------------------------
__device__ __forceinline__ uint32_t tf32_of(float x) {
    uint32_t r;
    asm("cvt.rna.tf32.f32 %0, %1;" : "=r"(r) : "f"(x));
    return r;
}
__device__ __forceinline__ void tf32_split(float x, uint32_t& hi, uint32_t& lo) {
    hi = tf32_of(x);
    lo = tf32_of(x - __uint_as_float(hi));
}
__device__ __forceinline__ void mma8(float* c, const uint32_t* a, const uint32_t* b) {
    asm volatile(
        "mma.sync.aligned.m16n8k8.row.col.f32.tf32.tf32.f32 "
        "{%0,%1,%2,%3},{%4,%5,%6,%7},{%8,%9},{%0,%1,%2,%3};"
        : "+f"(c[0]), "+f"(c[1]), "+f"(c[2]), "+f"(c[3])
        : "r"(a[0]), "r"(a[1]), "r"(a[2]), "r"(a[3]), "r"(b[0]), "r"(b[1]));
}

// ---------------- K1: foveate via pyramid; coalesced float4 row loads --------
// Patch p: size 14*2^p, window top-left 56-7*2^p: p0->49, p1->42, p2->28, p3->0
__global__ __launch_bounds__(512) void foveate_kernel(const float* __restrict__ x,
                                                      const float* __restrict__ loc) {
    __shared__ __align__(16) float rowbuf[16][132];  // per-warp 128-wide row sums
    __shared__ float L1[56 * L1W];
    __shared__ float L2[28 * L2W];
    __shared__ float ctr[14 * 15];

    int b = blockIdx.x;
    int t = threadIdx.x;
    int lane = t & 31, warp = t >> 5;   // 16 warps
    if (b == 0 && t < 256) {            // zero layer-1 stat accumulators
        g_sum1[t] = 0.f;
        g_sq1[t] = 0.f;
    }
    float lx = loc[2 * b + 0];
    float ly = loc[2 * b + 1];
    int cx = (int)(0.5f * ((lx + 1.0f) * 128.0f));
    int cy = (int)(0.5f * ((ly + 1.0f) * 128.0f));
    int wy0 = cy - 56, wx0 = cx - 56;
    const float* xb = x + (size_t)b * HH * HH;

    // L1 rows: warp handles rows warp, warp+16, warp+32, (+48 for warps 0-7).
    // Full image rows loaded as aligned float4 (coalesced), row-pair summed in
    // registers, parked in rowbuf, horizontal pairs via bounds-checked smem.
    for (int r = warp; r < 56; r += 16) {
        int gy0 = wy0 + 2 * r, gy1 = gy0 + 1;
        float4 v = make_float4(0.f, 0.f, 0.f, 0.f);
        if ((unsigned)gy0 < 128u) {
            v = ((const float4*)(xb + gy0 * HH))[lane];
        }
        if ((unsigned)gy1 < 128u) {
            float4 u = ((const float4*)(xb + gy1 * HH))[lane];
            v.x += u.x; v.y += u.y; v.z += u.z; v.w += u.w;
        }
        *(float4*)&rowbuf[warp][4 * lane] = v;
        __syncwarp();
        #pragma unroll
        for (int cc = 0; cc < 2; cc++) {
            int c = lane + cc * 32;
            if (c < 56) {
                int i0 = wx0 + 2 * c;
                int i1 = i0 + 1;
                float s = 0.f;
                if ((unsigned)i0 < 128u) s += rowbuf[warp][i0];
                if ((unsigned)i1 < 128u) s += rowbuf[warp][i1];
                L1[r * L1W + c] = s;
            }
        }
        __syncwarp();
    }
    // center 14x14 (patch0) raw pixels
    if (t < 196) {
        int i = t / 14, j = t - i * 14;
        int gy = wy0 + 49 + i, gx = wx0 + 49 + j;
        float v = 0.f;
        if (((unsigned)gy < 128u) & ((unsigned)gx < 128u)) v = xb[gy * HH + gx];
        ctr[i * 15 + j] = v;
    }
    __syncthreads();

    for (int i = t; i < 28 * 28; i += 512) {
        int r = i / 28, c = i - r * 28;
        const float* a0 = &L1[(2 * r) * L1W + 2 * c];
        const float* a1 = a0 + L1W;
        L2[r * L2W + c] = (a0[0] + a0[1]) + (a1[0] + a1[1]);
    }
    __syncthreads();

    for (int o = t; o < PHI_D; o += 512) {
        int p   = o / 196;
        int rem = o - p * 196;
        int i   = rem / 14;
        int j   = rem - i * 14;
        float v;
        if (p == 0) {
            v = ctr[i * 15 + j];
        } else if (p == 1) {
            v = L1[(21 + i) * L1W + 21 + j] * 0.25f;
        } else if (p == 2) {
            v = L2[(7 + i) * L2W + 7 + j] * 0.0625f;
        } else {
            const float* q0 = &L2[(2 * i) * L2W + 2 * j];
            const float* q1 = q0 + L2W;
            v = ((q0[0] + q0[1]) + (q1[0] + q1[1])) * (1.0f / 64.0f);
        }
        g_phi[(size_t)b * PHI_D + o] = v;
    }
}

// ---------------- K2: GEMM1 split-K(4), 3xTF32 mma ---------------------------
// 128 threads (4 warps 2x2). BM=64, BN=32, BK=16. Warp tile 32x16. grid (64,4,4).
__global__ __launch_bounds__(128) void gemm1_kernel(const float* __restrict__ W) {
    __shared__ float As[2][64 * 20];
    __shared__ float Bs[2][16 * 40];

    int t = threadIdx.x;
    int lane = t & 31, warp = t >> 5;
    int wm = warp >> 1, wn = warp & 1;
    int g = lane >> 2, tg = lane & 3;
    int rowBase = blockIdx.x * 64;
    int colBase = blockIdx.y * 32;
    int s = blockIdx.z;
    int t0 = (s == 0) ? 0 : 13 + 12 * (s - 1);   // 49 tiles: [13,12,12,12]
    int nt = (s == 0) ? 13 : 12;
    float* out = g_h1p + (size_t)s * SPLIT_OFF;

    int ar = t >> 1, ako = (t & 1) * 8;
    int bkr = t >> 3, bcc = (t & 7) * 4;

    float4 pa0, pa1, pb;
    float c[2][2][4] = {};

    auto fetch = [&](int kt) {
        const float* ap = &g_phi[(size_t)(rowBase + ar) * PHI_D + kt * 16 + ako];
        pa0 = *(const float4*)ap;
        pa1 = *(const float4*)(ap + 4);
        pb  = *(const float4*)&W[(size_t)(kt * 16 + bkr) * H1_D + colBase + bcc];
    };
    auto stage = [&](int buf) {
        float* a = &As[buf][ar * 20 + ako];
        *(float4*)a       = pa0;
        *(float4*)(a + 4) = pa1;
        *(float4*)&Bs[buf][bkr * 40 + bcc] = pb;
    };

    fetch(t0); stage(0); __syncthreads();
    int cur = 0;
    for (int i = 0; i < nt; i++) {
        if (i + 1 < nt) fetch(t0 + i + 1);
        #pragma unroll
        for (int ks = 0; ks < 2; ks++) {
            uint32_t ah[2][4], al[2][4], bh[2][2], bl[2][2];
            #pragma unroll
            for (int mt = 0; mt < 2; mt++) {
                int mrow = wm * 32 + mt * 16;
                #pragma unroll
                for (int r = 0; r < 4; r++) {
                    int row = mrow + g + (r & 1) * 8;
                    int col = ks * 8 + tg + (r >> 1) * 4;
                    tf32_split(As[cur][row * 20 + col], ah[mt][r], al[mt][r]);
                }
            }
            #pragma unroll
            for (int nt2 = 0; nt2 < 2; nt2++) {
                int ncol = wn * 16 + nt2 * 8 + g;
                #pragma unroll
                for (int r = 0; r < 2; r++)
                    tf32_split(Bs[cur][(ks * 8 + tg + r * 4) * 40 + ncol],
                               bh[nt2][r], bl[nt2][r]);
            }
            #pragma unroll
            for (int mt = 0; mt < 2; mt++)
                #pragma unroll
                for (int nt2 = 0; nt2 < 2; nt2++) {
                    mma8(c[mt][nt2], ah[mt], bh[nt2]);
                    mma8(c[mt][nt2], ah[mt], bl[nt2]);
                    mma8(c[mt][nt2], al[mt], bh[nt2]);
                }
        }
        if (i + 1 < nt) {
            int nxt = cur ^ 1;
            stage(nxt);
            __syncthreads();
            cur = nxt;
        }
    }
    #pragma unroll
    for (int mt = 0; mt < 2; mt++) {
        int r0 = rowBase + wm * 32 + mt * 16 + g;
        #pragma unroll
        for (int nt2 = 0; nt2 < 2; nt2++) {
            int col = colBase + wn * 16 + nt2 * 8 + 2 * tg;
            *(float2*)&g_h1p[(size_t)s * SPLIT_OFF + (size_t)r0 * H1_D + col] =
                make_float2(c[mt][nt2][0], c[mt][nt2][1]);
            *(float2*)&g_h1p[(size_t)s * SPLIT_OFF + (size_t)(r0 + 8) * H1_D + col] =
                make_float2(c[mt][nt2][2], c[mt][nt2][3]);
        }
    }
    (void)out;
}

// ---------------- K3: merge split-K partials -> g_h1 + column stats ----------
__global__ void stats1_kernel(const float* __restrict__ loc,
                              const float* __restrict__ Ww1) {
    int t = threadIdx.x;
    int row0 = blockIdx.x * 16;    // grid 256
    int col = t & 127;
    int rh = t >> 7;

    if (blockIdx.x == 0 && t < 256) {
        g_sum2[t] = 0.f; g_sum2[t + 256] = 0.f;
        g_sq2[t] = 0.f;  g_sq2[t + 256] = 0.f;
    }

    float s = 0.f, q = 0.f;
    #pragma unroll
    for (int r = 0; r < 16; r += 2) {
        int idx = (row0 + r + rh) * H1_D + col;
        float v = 0.f;
        #pragma unroll
        for (int k = 0; k < NSPLIT; k++) v += g_h1p[idx + k * SPLIT_OFF];
        g_h1[idx] = v;
        s += v; q += v * v;
    }
    atomicAdd(&g_sum1[col], s); atomicAdd(&g_sq1[col], q);

    float w0 = Ww1[col], w1 = Ww1[H1_D + col];
    s = 0.f; q = 0.f;
    #pragma unroll
    for (int r = 0; r < 16; r += 2) {
        int b = row0 + r + rh;
        float v = loc[2 * b] * w0 + loc[2 * b + 1] * w1;
        s += v; q += v * v;
    }
    atomicAdd(&g_sum1[H1_D + col], s); atomicAdd(&g_sq1[H1_D + col], q);
}

// ---------------- K4: GEMM2 both paths, 3xTF32 mma; BN+relu; stats2 fused ----
// 256 threads (8 warps 4x2). BM=128, BN=64, BK=16. Warp tile 32x32.
__global__ __launch_bounds__(256) void gemm2_kernel(
        const float* __restrict__ W2,     // (128,256)
        const float* __restrict__ Ww2,    // (128,256)
        const float* __restrict__ loc,
        const float* __restrict__ Ww1,    // (2,128)
        const float* __restrict__ g1, const float* __restrict__ be1,
        const float* __restrict__ gw1, const float* __restrict__ bew1) {
    __shared__ float As[2][128 * 20];    // 20.5KB
    __shared__ float Bs[2][16 * 72];     // 9.2KB
    __shared__ float scs[H1_D], shs[H1_D];
    __shared__ float2 red[8][64];        // 4KB: per-warp column partials

    int path = blockIdx.z;
    const float* W   = path ? Ww2  : W2;
    float*       out = path ? g_h2w : g_h2;
    int soff = path * H1_D;

    int t = threadIdx.x;
    int lane = t & 31, warp = t >> 5;
    int wm = warp >> 1, wn = warp & 1;
    int g = lane >> 2, tg = lane & 3;
    int rowBase = blockIdx.x * 128;
    int colBase = blockIdx.y * 64;

    if (t < H1_D) {
        float mean = g_sum1[soff + t] * (1.0f / 4096.0f);
        float var  = g_sq1[soff + t] * (1.0f / 4096.0f) - mean * mean;
        float gam = path ? gw1[t] : g1[t];
        float bet = path ? bew1[t] : be1[t];
        float sc = gam * rsqrtf(var + EPS);
        scs[t] = sc;
        shs[t] = bet - mean * sc;
    }

    int ar = t >> 1, ako = (t & 1) * 8;
    int bkr = t >> 4, bcc = (t & 15) * 4;
    float lx = 0.f, ly = 0.f;
    if (path) { lx = loc[2 * (rowBase + ar)]; ly = loc[2 * (rowBase + ar) + 1]; }

    float4 pa[2], pb;
    float c[2][4][4] = {};

    auto fetch = [&](int kt) {
        int k0 = kt * 16 + ako;
        if (path == 0) {
            const float* ap = &g_h1[(size_t)(rowBase + ar) * H1_D + k0];
            pa[0] = *(const float4*)ap;
            pa[1] = *(const float4*)(ap + 4);
        } else {
            #pragma unroll
            for (int j = 0; j < 2; j++) {
                float4 w0 = *(const float4*)&Ww1[k0 + j * 4];
                float4 w1 = *(const float4*)&Ww1[H1_D + k0 + j * 4];
                pa[j] = make_float4(lx * w0.x + ly * w1.x, lx * w0.y + ly * w1.y,
                                    lx * w0.z + ly * w1.z, lx * w0.w + ly * w1.w);
            }
        }
        pb = *(const float4*)&W[(size_t)(kt * 16 + bkr) * H2_D + colBase + bcc];
    };
    auto stage = [&](int kt, int buf) {
        int k0 = kt * 16 + ako;
        float* a = &As[buf][ar * 20 + ako];
        #pragma unroll
        for (int j = 0; j < 2; j++) {
            float4 v = pa[j];
            float4 sc4 = *(const float4*)&scs[k0 + j * 4];
            float4 sh4 = *(const float4*)&shs[k0 + j * 4];
            float4 r;
            r.x = fmaxf(v.x * sc4.x + sh4.x, 0.f);
            r.y = fmaxf(v.y * sc4.y + sh4.y, 0.f);
            r.z = fmaxf(v.z * sc4.z + sh4.z, 0.f);
            r.w = fmaxf(v.w * sc4.w + sh4.w, 0.f);
            *(float4*)(a + j * 4) = r;
        }
        *(float4*)&Bs[buf][bkr * 72 + bcc] = pb;
    };

    fetch(0);
    __syncthreads();
    stage(0, 0);
    __syncthreads();
    int cur = 0;
    const int NC = H1_D / 16;   // 8
    for (int i = 0; i < NC; i++) {
        if (i + 1 < NC) fetch(i + 1);
        #pragma unroll
        for (int ks = 0; ks < 2; ks++) {
            uint32_t ah[2][4], al[2][4], bh[4][2], bl[4][2];
            #pragma unroll
            for (int mt = 0; mt < 2; mt++) {
                int mrow = wm * 32 + mt * 16;
                #pragma unroll
                for (int r = 0; r < 4; r++) {
                    int row = mrow + g + (r & 1) * 8;
                    int col = ks * 8 + tg + (r >> 1) * 4;
                    tf32_split(As[cur][row * 20 + col], ah[mt][r], al[mt][r]);
                }
            }
            #pragma unroll
            for (int nt = 0; nt < 4; nt++) {
                int ncol = wn * 32 + nt * 8 + g;
                #pragma unroll
                for (int r = 0; r < 2; r++)
                    tf32_split(Bs[cur][(ks * 8 + tg + r * 4) * 72 + ncol],
                               bh[nt][r], bl[nt][r]);
            }
            #pragma unroll
            for (int mt = 0; mt < 2; mt++)
                #pragma unroll
                for (int nt = 0; nt < 4; nt++) {
                    mma8(c[mt][nt], ah[mt], bh[nt]);
                    mma8(c[mt][nt], ah[mt], bl[nt]);
                    mma8(c[mt][nt], al[mt], bh[nt]);
                }
        }
        if (i + 1 < NC) {
            int nxt = cur ^ 1;
            stage(i + 1, nxt);
            __syncthreads();
            cur = nxt;
        }
    }
    #pragma unroll
    for (int mt = 0; mt < 2; mt++) {
        int r0 = rowBase + wm * 32 + mt * 16 + g;
        #pragma unroll
        for (int nt = 0; nt < 4; nt++) {
            int col = colBase + wn * 32 + nt * 8 + 2 * tg;
            *(float2*)&out[(size_t)r0 * H2_D + col] =
                make_float2(c[mt][nt][0], c[mt][nt][1]);
            *(float2*)&out[(size_t)(r0 + 8) * H2_D + col] =
                make_float2(c[mt][nt][2], c[mt][nt][3]);
        }
    }

    // fused column stats: xor-shuffle across g-groups, per-warp red[], atomics.
    #pragma unroll
    for (int nt = 0; nt < 4; nt++) {
        #pragma unroll
        for (int j = 0; j < 2; j++) {
            float a0 = c[0][nt][j],     a1 = c[0][nt][j + 2];
            float a2 = c[1][nt][j],     a3 = c[1][nt][j + 2];
            float s = a0 + a1 + a2 + a3;
            float q = a0 * a0 + a1 * a1 + a2 * a2 + a3 * a3;
            s += __shfl_xor_sync(0xffffffff, s, 4);
            q += __shfl_xor_sync(0xffffffff, q, 4);
            s += __shfl_xor_sync(0xffffffff, s, 8);
            q += __shfl_xor_sync(0xffffffff, q, 8);
            s += __shfl_xor_sync(0xffffffff, s, 16);
            q += __shfl_xor_sync(0xffffffff, q, 16);
            if (g == 0)
                red[warp][wn * 32 + nt * 8 + 2 * tg + j] = make_float2(s, q);
        }
    }
    __syncthreads();
    if (t < 64) {
        int w0 = (t >= 32) ? 1 : 0;
        float s = 0.f, q = 0.f;
        #pragma unroll
        for (int k = 0; k < 4; k++) {
            float2 v = red[w0 + 2 * k][t];
            s += v.x; q += v.y;
        }
        int col = path * H2_D + colBase + t;
        atomicAdd(&g_sum2[col], s);
        atomicAdd(&g_sq2[col], q);
    }
}

// ---------------- K6: out = relu(BN(h2) + BN(h2w)) ---------------------------
__global__ void final_kernel(const float* __restrict__ g2, const float* __restrict__ be2,
                             const float* __restrict__ gw2, const float* __restrict__ bew2,
                             float* __restrict__ out) {
    int idx = blockIdx.x * blockDim.x + threadIdx.x;
    int c = idx & 255;
    float m0 = g_sum2[c] * (1.0f / 4096.0f);
    float v0 = g_sq2[c] * (1.0f / 4096.0f) - m0 * m0;
    float s0 = g2[c] * rsqrtf(v0 + EPS);
    float h0 = be2[c] - m0 * s0;
    float m1 = g_sum2[256 + c] * (1.0f / 4096.0f);
    float v1 = g_sq2[256 + c] * (1.0f / 4096.0f) - m1 * m1;
    float s1 = gw2[c] * rsqrtf(v1 + EPS);
    float h1 = bew2[c] - m1 * s1;
    float a = g_h2[idx]  * s0 + h0;
    float b = g_h2w[idx] * s1 + h1;
    out[idx] = fmaxf(a + b, 0.f);
}

// ---------------- launch -----------------------------------------------------
extern "C" void kernel_launch(void* const* d_in, const int* in_sizes, int n_in,
                              void* d_out, int out_size) {
    const float* x        = (const float*)d_in[0];
    const float* loc      = (const float*)d_in[1];
    const float* what_W1  = (const float*)d_in[2];
    const float* what_g1  = (const float*)d_in[4];
    const float* what_be1 = (const float*)d_in[5];
    const float* what_W2  = (const float*)d_in[6];
    const float* what_g2  = (const float*)d_in[8];
    const float* what_be2 = (const float*)d_in[9];
    const float* where_W1  = (const float*)d_in[10];
    const float* where_g1  = (const float*)d_in[12];
    const float* where_be1 = (const float*)d_in[13];
    const float* where_W2  = (const float*)d_in[14];
    const float* where_g2  = (const float*)d_in[16];
    const float* where_be2 = (const float*)d_in[17];
    float* out = (float*)d_out;

    foveate_kernel<<<B_SZ, 512>>>(x, loc);
    gemm1_kernel<<<dim3(B_SZ / 64, H1_D / 32, NSPLIT), 128>>>(what_W1);
    stats1_kernel<<<256, 256>>>(loc, where_W1);
    gemm2_kernel<<<dim3(B_SZ / 128, H2_D / 64, 2), 256>>>(
        what_W2, where_W2, loc, where_W1,
        what_g1, what_be1, where_g1, where_be1);
    final_kernel<<<(B_SZ * H2_D) / 512, 512>>>(
        what_g2, what_be2, where_g2, where_be2, out);
}